// round 13
// baseline (speedup 1.0000x reference)
#include <cuda_runtime.h>
#include <cuda_bf16.h>
#include <cstdint>

#define EPSV 1e-5f

typedef unsigned long long ull;

// ---------------- scratch buffers (static, allocation-free) ----------------
__device__ __nv_bfloat16 g_xth[225 * 256 * 256]; // x transposed+split: [ij][m][ck<=255]
__device__ __nv_bfloat16 g_xtl[225 * 256 * 256];
__device__ __nv_bfloat16 g_B1h[225 * 128 * 256]; // per-ij conv1 B matrices, split
__device__ __nv_bfloat16 g_B1l[225 * 128 * 256];
__device__ __nv_bfloat16 g_y1h[256 * 225 * 128]; // y1 split, ch-last (m, sp, c)
__device__ __nv_bfloat16 g_y1l[256 * 225 * 128];
__device__ __nv_bfloat16 g_w2h[128 * 6272];      // w2 split: [n][(kh*7+kw)*128+ci]
__device__ __nv_bfloat16 g_w2l[128 * 6272];
__device__ float         g_x2f[20736 * 128];     // x_ fp32 ch-last [m][c] (for k5)
__device__ __nv_bfloat16 g_a3h[20736 * 144];     // k3 A operand split: [m][144]
__device__ __nv_bfloat16 g_a3l[20736 * 144];
__device__ __nv_bfloat16 g_w3h[128 * 144];
__device__ __nv_bfloat16 g_w3l[128 * 144];
__device__ __nv_bfloat16 g_y3h[20736 * 128];
__device__ __nv_bfloat16 g_y3l[20736 * 128];
__device__ __nv_bfloat16 g_w4h[128 * 128];
__device__ __nv_bfloat16 g_w4l[128 * 128];
__device__ float         g_merge[20736 * 128];   // fp32 ch-last [m][c]
__device__ float         g_logits[20736];

// ---------------- PTX helpers (baseline sm_80+) ----------------
__device__ __forceinline__ uint32_t smem_u32(const void* p) {
    uint32_t a;
    asm("{ .reg .u64 t; cvta.to.shared.u64 t, %1; cvt.u32.u64 %0, t; }" : "=r"(a) : "l"(p));
    return a;
}
__device__ __forceinline__ void cpa16(uint32_t dst, const void* src) {
    asm volatile("cp.async.ca.shared.global [%0], [%1], 16;" :: "r"(dst), "l"(src));
}
#define CP_COMMIT() asm volatile("cp.async.commit_group;" ::: "memory")
#define CP_WAIT2()  asm volatile("cp.async.wait_group 2;" ::: "memory")
#define CP_WAIT1()  asm volatile("cp.async.wait_group 1;" ::: "memory")
#define CP_WAIT0()  asm volatile("cp.async.wait_group 0;" ::: "memory")

__device__ __forceinline__ void ldsm4(uint32_t* r, uint32_t addr) {
    asm volatile("ldmatrix.sync.aligned.m8n8.x4.shared.b16 {%0,%1,%2,%3}, [%4];"
                 : "=r"(r[0]), "=r"(r[1]), "=r"(r[2]), "=r"(r[3]) : "r"(addr));
}
__device__ __forceinline__ void mma16816(float* d, const uint32_t* a, const uint32_t* b) {
    asm volatile(
        "mma.sync.aligned.m16n8k16.row.col.f32.bf16.bf16.f32 "
        "{%0,%1,%2,%3}, {%4,%5,%6,%7}, {%8,%9}, {%0,%1,%2,%3};"
        : "+f"(d[0]), "+f"(d[1]), "+f"(d[2]), "+f"(d[3])
        : "r"(a[0]), "r"(a[1]), "r"(a[2]), "r"(a[3]), "r"(b[0]), "r"(b[1]));
}
__device__ __forceinline__ uint32_t cvt2(float f0, float f1) {
    uint32_t r;
    asm("cvt.rn.bf16x2.f32 %0, %1, %2;" : "=r"(r) : "f"(f1), "f"(f0));
    return r;
}
__device__ __forceinline__ void split2(float v0, float v1, uint32_t& h, uint32_t& lo) {
    h = cvt2(v0, v1);
    float r0 = v0 - __uint_as_float(h << 16);
    float r1 = v1 - __uint_as_float(h & 0xFFFF0000u);
    lo = cvt2(r0, r1);
}

// ============================================================================
// prepA: merged kX (x transpose+split) + kB (per-ij B1 matrices)
// ============================================================================
__global__ __launch_bounds__(256) void prepA(const float* __restrict__ x,
                                             const float* __restrict__ w1)
{
    const int b = blockIdx.x;
    if (b < 2048) {
        __shared__ float s[225][33];
        const int tid = threadIdx.x;
        const int tx = tid & 31, ty = tid >> 5;
        const int ij0 = (b & 7) * 32;
        const int m   = b >> 3;
        const int nij = (ij0 + 32 <= 225) ? 32 : (225 - ij0);

        const float* xp = x + (long)m * 50625;
        for (int cc = 0; cc < 29; cc++) {
            int c = cc * 8 + ty;
            if (c < 225) {
                float v = (tx < nij) ? xp[c * 225 + ij0 + tx] : 0.f;
                s[c][tx] = v;
            }
        }
        __syncthreads();
        for (int ii = 0; ii < nij; ii++) {
            float v = (tid < 225) ? s[tid][ii] : 0.f;
            __nv_bfloat16 h = __float2bfloat16(v);
            long idx = ((long)(ij0 + ii) * 256 + m) * 256 + tid;
            g_xth[idx] = h;
            g_xtl[idx] = __float2bfloat16(v - __bfloat162float(h));
        }
    } else {
        const int bid = b - 2048;
        const int ij = bid >> 7, n = bid & 127;
        const int ip = ij / 15, jp = ij - ip * 15;
        const int k = threadIdx.x;
        float v = 0.f;
        if (k < 225) {
            int a = k / 15, bb = k - a * 15;
            v = w1[n * 841 + (a + 14 - ip) * 29 + (bb + 14 - jp)];
        }
        __nv_bfloat16 h = __float2bfloat16(v);
        long idx = ((long)ij * 128 + n) * 256 + k;
        g_B1h[idx] = h;
        g_B1l[idx] = __float2bfloat16(v - __bfloat162float(h));
    }
}

// ============================================================================
// prepB: merged kT2 + kT3 + kT4 + kF.  grid 4568, block 256
// ============================================================================
__global__ __launch_bounds__(256) void prepB(const float* __restrict__ w2,
                                             const float* __restrict__ w3,
                                             const float* __restrict__ w4,
                                             const float* __restrict__ wgt)
{
    const int b = blockIdx.x;
    if (b < 3136) {
        int t = b * 256 + threadIdx.x;
        if (t < 128 * 6272) {
            int n = t / 6272, k = t - n * 6272;
            int g = k >> 7, ci = k & 127;
            float v = w2[n * 6272 + ci * 49 + g];
            __nv_bfloat16 h = __float2bfloat16(v);
            g_w2h[t] = h;
            g_w2l[t] = __float2bfloat16(v - __bfloat162float(h));
        }
    } else if (b < 3136 + 72) {
        int t = (b - 3136) * 256 + threadIdx.x;
        if (t < 128 * 144) {
            int n = t / 144, j = t - n * 144;
            float v = 0.f;
            if (j < 5)                  v = w3[n * 133 + j];
            else if (j >= 8 && j < 136) v = w3[n * 133 + j - 3];
            __nv_bfloat16 h = __float2bfloat16(v);
            g_w3h[t] = h;
            g_w3l[t] = __float2bfloat16(v - __bfloat162float(h));
        }
    } else if (b < 3136 + 72 + 64) {
        int t = (b - 3136 - 72) * 256 + threadIdx.x;
        if (t < 128 * 128) {
            float v = w4[t];
            __nv_bfloat16 h = __float2bfloat16(v);
            g_w4h[t] = h;
            g_w4l[t] = __float2bfloat16(v - __bfloat162float(h));
        }
    } else {
        int t = (b - 3136 - 72 - 64) * 256 + threadIdx.x;
        if (t < 20736 * 16) {
            int m = t >> 4, jj = t & 15;
            int j = (jj < 8) ? jj : (128 + jj);
            float v = (j < 5) ? wgt[j * 81 + (m % 81)] : 0.f;
            __nv_bfloat16 h = __float2bfloat16(v);
            long idx = (long)m * 144 + j;
            g_a3h[idx] = h;
            g_a3l[idx] = __float2bfloat16(v - __bfloat162float(h));
        }
    }
}

// ============================================================================
// k1: align-conv1 as MMA (R9-proven).  per ij: M=256, N=128, K=256(padded).
// grid (225, 2), block 256.  4 stages KT=64, double-buffered, 147KB.
// ============================================================================
#define LDA1    144
#define T1PLANE (128 * 144)
#define STAGE1  (4 * T1PLANE)
#define K1_SMEM (2 * STAGE1)       // 147456

__global__ __launch_bounds__(256) void k1_mma(
    const float* __restrict__ b1, const float* __restrict__ bn1)
{
    extern __shared__ char smem[];
    const uint32_t sb = smem_u32(smem);
    const int tid = threadIdx.x;
    const int w = tid >> 5, l = tid & 31;
    const int ij = blockIdx.x;
    const int m0 = blockIdx.y * 128;
    const int warp_m = (w >> 2) * 64;
    const int warp_n = (w & 3) * 32;

    const int row = tid & 127, ver = tid >> 7;
    const __nv_bfloat16* asrc = (ver ? g_xtl : g_xth) + ((long)ij * 256 + m0 + row) * 256;
    const __nv_bfloat16* bsrc = (ver ? g_B1l : g_B1h) + ((long)ij * 128 + row) * 256;
    const uint32_t dA = sb + ver * T1PLANE + row * LDA1;
    const uint32_t dB = sb + 2 * T1PLANE + ver * T1PLANE + row * LDA1;

    float acc[4][4][4];
#pragma unroll
    for (int i = 0; i < 4; i++)
#pragma unroll
        for (int j = 0; j < 4; j++)
#pragma unroll
            for (int c = 0; c < 4; c++) acc[i][j][c] = 0.f;

    auto load_stage = [&](int s, uint32_t off) {
#pragma unroll
        for (int j = 0; j < 8; j++) {
            cpa16(dA + off + j * 16, asrc + s * 64 + j * 8);
            cpa16(dB + off + j * 16, bsrc + s * 64 + j * 8);
        }
    };

    const uint32_t aAddrM = (warp_m + (l & 15)) * LDA1 + ((l >> 4) << 4);
    const uint32_t bAddrN = (warp_n + (l & 7) + ((l >> 4) << 3)) * LDA1 + (((l >> 3) & 1) << 4);
    auto compute_stage = [&](uint32_t off) {
        uint32_t base = sb + off;
#pragma unroll
        for (int ks = 0; ks < 4; ks++) {
            uint32_t ko = ks * 32;
            uint32_t ah[4][4], al[4][4];
#pragma unroll
            for (int mi = 0; mi < 4; mi++) {
                uint32_t ad = base + aAddrM + mi * (16 * LDA1) + ko;
                ldsm4(ah[mi], ad);
                ldsm4(al[mi], ad + T1PLANE);
            }
            uint32_t bh[2][4], bl[2][4];
#pragma unroll
            for (int nb = 0; nb < 2; nb++) {
                uint32_t bd = base + 2 * T1PLANE + bAddrN + nb * (16 * LDA1) + ko;
                ldsm4(bh[nb], bd);
                ldsm4(bl[nb], bd + T1PLANE);
            }
#pragma unroll
            for (int mi = 0; mi < 4; mi++)
#pragma unroll
                for (int nj = 0; nj < 4; nj++)
                    mma16816(acc[mi][nj], ah[mi], &bh[nj >> 1][(nj & 1) * 2]);
#pragma unroll
            for (int mi = 0; mi < 4; mi++)
#pragma unroll
                for (int nj = 0; nj < 4; nj++)
                    mma16816(acc[mi][nj], ah[mi], &bl[nj >> 1][(nj & 1) * 2]);
#pragma unroll
            for (int mi = 0; mi < 4; mi++)
#pragma unroll
                for (int nj = 0; nj < 4; nj++)
                    mma16816(acc[mi][nj], al[mi], &bh[nj >> 1][(nj & 1) * 2]);
        }
    };

    load_stage(0, 0);
    CP_COMMIT();
    for (int s = 0; s < 4; s++) {
        if (s + 1 < 4) load_stage(s + 1, ((s + 1) & 1) * STAGE1);
        CP_COMMIT();
        CP_WAIT1();
        __syncthreads();
        compute_stage((s & 1) * STAGE1);
        __syncthreads();
    }

    float sc[4][2], sh[4][2];
#pragma unroll
    for (int nj = 0; nj < 4; nj++)
#pragma unroll
        for (int q = 0; q < 2; q++) {
            int n = warp_n + nj * 8 + (l & 3) * 2 + q;
            float g = bn1[n], be = bn1[128 + n], mu = bn1[256 + n], va = bn1[384 + n];
            float s = g * rsqrtf(va + EPSV);
            sc[nj][q] = s;
            sh[nj][q] = (b1[n] - mu) * s + be;
        }
#pragma unroll
    for (int mi = 0; mi < 4; mi++)
#pragma unroll
        for (int half = 0; half < 2; half++) {
            int m = m0 + warp_m + mi * 16 + (l >> 2) + half * 8;
            long base = ((long)m * 225 + ij) * 128;
#pragma unroll
            for (int nj = 0; nj < 4; nj++) {
                int n0 = warp_n + nj * 8 + (l & 3) * 2;
                float v0 = fmaxf(fmaf(acc[mi][nj][half * 2 + 0], sc[nj][0], sh[nj][0]), 0.f);
                float v1 = fmaxf(fmaf(acc[mi][nj][half * 2 + 1], sc[nj][1], sh[nj][1]), 0.f);
                uint32_t h, lo;
                split2(v0, v1, h, lo);
                *(uint32_t*)&g_y1h[base + n0] = h;
                *(uint32_t*)&g_y1l[base + n0] = lo;
            }
        }
}

// ============================================================================
// k2: 7x7 conv MMA, M=20736 N=128 K=6272.  128x128 tile, 256 threads,
// 4-stage cp.async ring + FULL FRAGMENT PREFETCH: all 24 LDSM (both ksteps)
// issued before the 96 MMAs -> LDSM latency exposed once per stage.
// grid 162.
// ============================================================================
#define LDA    80
#define TILE_V 10240
#define STAGE  40960
#define K2_SMEM (4 * STAGE)        // 163840

__global__ __launch_bounds__(256, 1) void k2_mma(
    const float* __restrict__ b2, const float* __restrict__ bn2)
{
    extern __shared__ char smem[];
    const uint32_t sb = smem_u32(smem);
    const int tid = threadIdx.x;
    const int w = tid >> 5, l = tid & 31;
    const int m0 = blockIdx.x * 128;
    const int warp_m = (w >> 2) * 64;
    const int warp_n = (w & 3) * 32;

    const int lr = tid >> 1;
    const int lob = (tid & 1) * 32;
    const int loe = lob >> 1;
    const int gm = m0 + lr;
    const int bv = gm / 81;
    const int pos = gm - bv * 81;
    const int oh = pos / 9, ow = pos - oh * 9;
    const long a_base = ((long)bv * 225 + oh * 15 + ow) * 128;
    const __nv_bfloat16* wh_src = g_w2h + (long)lr * 6272;
    const __nv_bfloat16* wl_src = g_w2l + (long)lr * 6272;
    const uint32_t dstA = sb + lr * LDA + lob;
    const uint32_t dstB = sb + 2 * TILE_V + lr * LDA + lob;

    float acc[4][4][4];
#pragma unroll
    for (int i = 0; i < 4; i++)
#pragma unroll
        for (int j = 0; j < 4; j++)
#pragma unroll
            for (int c = 0; c < 4; c++) acc[i][j][c] = 0.f;

    auto load_stage = [&](int s, uint32_t bufoff) {
        int g  = s >> 2;
        int kh = g / 7, kw = g - kh * 7;
        long aoff = a_base + (kh * 15 + kw) * 128 + (s & 3) * 32 + loe;
        const __nv_bfloat16* pah = g_y1h + aoff;
        const __nv_bfloat16* pal = g_y1l + aoff;
        uint32_t dA = dstA + bufoff;
        cpa16(dA, pah);
        cpa16(dA + 16, pah + 8);
        cpa16(dA + TILE_V, pal);
        cpa16(dA + TILE_V + 16, pal + 8);
        long boff = (long)s * 32 + loe;
        uint32_t dB = dstB + bufoff;
        cpa16(dB, wh_src + boff);
        cpa16(dB + 16, wh_src + boff + 8);
        cpa16(dB + TILE_V, wl_src + boff);
        cpa16(dB + TILE_V + 16, wl_src + boff + 8);
    };

    const uint32_t aAddrM = (warp_m + (l & 15)) * LDA + ((l >> 4) << 4);
    const uint32_t bAddrN = (warp_n + (l & 7) + ((l >> 4) << 3)) * LDA + (((l >> 3) & 1) << 4);
    auto compute_stage = [&](uint32_t bufoff) {
        uint32_t base = sb + bufoff;
        // ---- prefetch ALL fragments for both ksteps ----
        uint32_t ah[2][4][4], al[2][4][4];
        uint32_t bh[2][2][4], bl[2][2][4];
#pragma unroll
        for (int ks = 0; ks < 2; ks++) {
            uint32_t ko = ks * 32;
#pragma unroll
            for (int mi = 0; mi < 4; mi++) {
                uint32_t ad = base + aAddrM + mi * (16 * LDA) + ko;
                ldsm4(ah[ks][mi], ad);
                ldsm4(al[ks][mi], ad + TILE_V);
            }
#pragma unroll
            for (int nb = 0; nb < 2; nb++) {
                uint32_t bd = base + 2 * TILE_V + bAddrN + nb * (16 * LDA) + ko;
                ldsm4(bh[ks][nb], bd);
                ldsm4(bl[ks][nb], bd + TILE_V);
            }
        }
        // ---- stream 96 MMAs ----
#pragma unroll
        for (int ks = 0; ks < 2; ks++) {
#pragma unroll
            for (int mi = 0; mi < 4; mi++)
#pragma unroll
                for (int nj = 0; nj < 4; nj++)
                    mma16816(acc[mi][nj], ah[ks][mi], &bh[ks][nj >> 1][(nj & 1) * 2]);
#pragma unroll
            for (int mi = 0; mi < 4; mi++)
#pragma unroll
                for (int nj = 0; nj < 4; nj++)
                    mma16816(acc[mi][nj], ah[ks][mi], &bl[ks][nj >> 1][(nj & 1) * 2]);
#pragma unroll
            for (int mi = 0; mi < 4; mi++)
#pragma unroll
                for (int nj = 0; nj < 4; nj++)
                    mma16816(acc[mi][nj], al[ks][mi], &bh[ks][nj >> 1][(nj & 1) * 2]);
        }
    };

    // ---- 4-deep pipeline: 3 stages in flight ahead of compute ----
    load_stage(0, 0);           CP_COMMIT();
    load_stage(1, STAGE);       CP_COMMIT();
    load_stage(2, 2 * STAGE);   CP_COMMIT();
    for (int s = 0; s < 196; s++) {
        CP_WAIT2();
        __syncthreads();
        compute_stage((s & 3) * STAGE);
        if (s + 3 < 196) load_stage(s + 3, ((s + 3) & 3) * STAGE);
        CP_COMMIT();
    }

    float sc[4][2], sh[4][2];
#pragma unroll
    for (int nj = 0; nj < 4; nj++)
#pragma unroll
        for (int q = 0; q < 2; q++) {
            int n = warp_n + nj * 8 + (l & 3) * 2 + q;
            float g = bn2[n], be = bn2[128 + n], mu = bn2[256 + n], va = bn2[384 + n];
            float s = g * rsqrtf(va + EPSV);
            sc[nj][q] = s;
            sh[nj][q] = (b2[n] - mu) * s + be;
        }
#pragma unroll
    for (int mi = 0; mi < 4; mi++)
#pragma unroll
        for (int half = 0; half < 2; half++) {
            int m = m0 + warp_m + mi * 16 + (l >> 2) + half * 8;
#pragma unroll
            for (int nj = 0; nj < 4; nj++) {
                int n0 = warp_n + nj * 8 + (l & 3) * 2;
                float v0 = fmaxf(fmaf(acc[mi][nj][half * 2 + 0], sc[nj][0], sh[nj][0]), 0.f);
                float v1 = fmaxf(fmaf(acc[mi][nj][half * 2 + 1], sc[nj][1], sh[nj][1]), 0.f);
                *(float2*)&g_x2f[(long)m * 128 + n0] = make_float2(v0, v1);
                uint32_t h, lo;
                split2(v0, v1, h, lo);
                *(uint32_t*)&g_a3h[(long)m * 144 + 8 + n0] = h;
                *(uint32_t*)&g_a3l[(long)m * 144 + 8 + n0] = lo;
            }
        }
}

// ============================================================================
// k3: conv1x1 144->128 MMA (monolithic smem), grid 162, block 256
// ============================================================================
#define LDA3    304
#define T3PLANE (128 * 304)
#define K3_SMEM (4 * T3PLANE)

__global__ __launch_bounds__(256) void k3_mma(
    const float* __restrict__ b3, const float* __restrict__ bn3)
{
    extern __shared__ char smem[];
    const uint32_t sb = smem_u32(smem);
    const int tid = threadIdx.x;
    const int w = tid >> 5, l = tid & 31;
    const int m0 = blockIdx.x * 128;
    const int warp_m = (w >> 2) * 64;
    const int warp_n = (w & 3) * 32;

    const int row = tid & 127, ver = tid >> 7;
    const __nv_bfloat16* asrc = (ver ? g_a3l : g_a3h) + (long)(m0 + row) * 144;
    const __nv_bfloat16* bsrc = (ver ? g_w3l : g_w3h) + row * 144;
    const uint32_t dA = sb + ver * T3PLANE + row * LDA3;
    const uint32_t dB = sb + 2 * T3PLANE + ver * T3PLANE + row * LDA3;
#pragma unroll
    for (int j = 0; j < 18; j++) {
        cpa16(dA + j * 16, asrc + j * 8);
        cpa16(dB + j * 16, bsrc + j * 8);
    }
    CP_COMMIT();

    float acc[4][4][4];
#pragma unroll
    for (int i = 0; i < 4; i++)
#pragma unroll
        for (int j = 0; j < 4; j++)
#pragma unroll
            for (int c = 0; c < 4; c++) acc[i][j][c] = 0.f;

    CP_WAIT0();
    __syncthreads();

    const uint32_t aAddrM = (warp_m + (l & 15)) * LDA3 + ((l >> 4) << 4);
    const uint32_t bAddrN = (warp_n + (l & 7) + ((l >> 4) << 3)) * LDA3 + (((l >> 3) & 1) << 4);
#pragma unroll
    for (int ks = 0; ks < 9; ks++) {
        uint32_t ko = ks * 32;
        uint32_t ah[4][4], al[4][4];
#pragma unroll
        for (int mi = 0; mi < 4; mi++) {
            uint32_t ad = sb + aAddrM + mi * (16 * LDA3) + ko;
            ldsm4(ah[mi], ad);
            ldsm4(al[mi], ad + T3PLANE);
        }
        uint32_t bh[2][4], bl[2][4];
#pragma unroll
        for (int nb = 0; nb < 2; nb++) {
            uint32_t bd = sb + 2 * T3PLANE + bAddrN + nb * (16 * LDA3) + ko;
            ldsm4(bh[nb], bd);
            ldsm4(bl[nb], bd + T3PLANE);
        }
#pragma unroll
        for (int mi = 0; mi < 4; mi++)
#pragma unroll
            for (int nj = 0; nj < 4; nj++)
                mma16816(acc[mi][nj], ah[mi], &bh[nj >> 1][(nj & 1) * 2]);
#pragma unroll
        for (int mi = 0; mi < 4; mi++)
#pragma unroll
            for (int nj = 0; nj < 4; nj++)
                mma16816(acc[mi][nj], ah[mi], &bl[nj >> 1][(nj & 1) * 2]);
#pragma unroll
        for (int mi = 0; mi < 4; mi++)
#pragma unroll
            for (int nj = 0; nj < 4; nj++)
                mma16816(acc[mi][nj], al[mi], &bh[nj >> 1][(nj & 1) * 2]);
    }

    float sc[4][2], sh[4][2];
#pragma unroll
    for (int nj = 0; nj < 4; nj++)
#pragma unroll
        for (int q = 0; q < 2; q++) {
            int n = warp_n + nj * 8 + (l & 3) * 2 + q;
            float g = bn3[n], be = bn3[128 + n], mu = bn3[256 + n], va = bn3[384 + n];
            float s = g * rsqrtf(va + EPSV);
            sc[nj][q] = s;
            sh[nj][q] = (b3[n] - mu) * s + be;
        }
#pragma unroll
    for (int mi = 0; mi < 4; mi++)
#pragma unroll
        for (int half = 0; half < 2; half++) {
            int m = m0 + warp_m + mi * 16 + (l >> 2) + half * 8;
#pragma unroll
            for (int nj = 0; nj < 4; nj++) {
                int n0 = warp_n + nj * 8 + (l & 3) * 2;
                float v0 = fmaxf(fmaf(acc[mi][nj][half * 2 + 0], sc[nj][0], sh[nj][0]), 0.f);
                float v1 = fmaxf(fmaf(acc[mi][nj][half * 2 + 1], sc[nj][1], sh[nj][1]), 0.f);
                uint32_t h, lo;
                split2(v0, v1, h, lo);
                *(uint32_t*)&g_y3h[(long)m * 128 + n0] = h;
                *(uint32_t*)&g_y3l[(long)m * 128 + n0] = lo;
            }
        }
}

// ============================================================================
// k4: conv1x1 128->128 MMA (monolithic smem) -> g_merge fp32 ch-last
// ============================================================================
#define LDA4    272
#define T4PLANE (128 * 272)
#define K4_SMEM (4 * T4PLANE)

__global__ __launch_bounds__(256) void k4_mma(
    const float* __restrict__ b4, const float* __restrict__ bn4)
{
    extern __shared__ char smem[];
    const uint32_t sb = smem_u32(smem);
    const int tid = threadIdx.x;
    const int w = tid >> 5, l = tid & 31;
    const int m0 = blockIdx.x * 128;
    const int warp_m = (w >> 2) * 64;
    const int warp_n = (w & 3) * 32;

    const int row = tid & 127, ver = tid >> 7;
    const __nv_bfloat16* asrc = (ver ? g_y3l : g_y3h) + (long)(m0 + row) * 128;
    const __nv_bfloat16* bsrc = (ver ? g_w4l : g_w4h) + row * 128;
    const uint32_t dA = sb + ver * T4PLANE + row * LDA4;
    const uint32_t dB = sb + 2 * T4PLANE + ver * T4PLANE + row * LDA4;
#pragma unroll
    for (int j = 0; j < 16; j++) {
        cpa16(dA + j * 16, asrc + j * 8);
        cpa16(dB + j * 16, bsrc + j * 8);
    }
    CP_COMMIT();

    float acc[4][4][4];
#pragma unroll
    for (int i = 0; i < 4; i++)
#pragma unroll
        for (int j = 0; j < 4; j++)
#pragma unroll
            for (int c = 0; c < 4; c++) acc[i][j][c] = 0.f;

    CP_WAIT0();
    __syncthreads();

    const uint32_t aAddrM = (warp_m + (l & 15)) * LDA4 + ((l >> 4) << 4);
    const uint32_t bAddrN = (warp_n + (l & 7) + ((l >> 4) << 3)) * LDA4 + (((l >> 3) & 1) << 4);
#pragma unroll
    for (int ks = 0; ks < 8; ks++) {
        uint32_t ko = ks * 32;
        uint32_t ah[4][4], al[4][4];
#pragma unroll
        for (int mi = 0; mi < 4; mi++) {
            uint32_t ad = sb + aAddrM + mi * (16 * LDA4) + ko;
            ldsm4(ah[mi], ad);
            ldsm4(al[mi], ad + T4PLANE);
        }
        uint32_t bh[2][4], bl[2][4];
#pragma unroll
        for (int nb = 0; nb < 2; nb++) {
            uint32_t bd = sb + 2 * T4PLANE + bAddrN + nb * (16 * LDA4) + ko;
            ldsm4(bh[nb], bd);
            ldsm4(bl[nb], bd + T4PLANE);
        }
#pragma unroll
        for (int mi = 0; mi < 4; mi++)
#pragma unroll
            for (int nj = 0; nj < 4; nj++)
                mma16816(acc[mi][nj], ah[mi], &bh[nj >> 1][(nj & 1) * 2]);
#pragma unroll
        for (int mi = 0; mi < 4; mi++)
#pragma unroll
            for (int nj = 0; nj < 4; nj++)
                mma16816(acc[mi][nj], ah[mi], &bl[nj >> 1][(nj & 1) * 2]);
#pragma unroll
        for (int mi = 0; mi < 4; mi++)
#pragma unroll
            for (int nj = 0; nj < 4; nj++)
                mma16816(acc[mi][nj], al[mi], &bh[nj >> 1][(nj & 1) * 2]);
    }

    float sc[4][2], sh[4][2];
#pragma unroll
    for (int nj = 0; nj < 4; nj++)
#pragma unroll
        for (int q = 0; q < 2; q++) {
            int n = warp_n + nj * 8 + (l & 3) * 2 + q;
            float g = bn4[n], be = bn4[128 + n], mu = bn4[256 + n], va = bn4[384 + n];
            float s = g * rsqrtf(va + EPSV);
            sc[nj][q] = s;
            sh[nj][q] = (b4[n] - mu) * s + be;
        }
#pragma unroll
    for (int mi = 0; mi < 4; mi++)
#pragma unroll
        for (int half = 0; half < 2; half++) {
            int m = m0 + warp_m + mi * 16 + (l >> 2) + half * 8;
#pragma unroll
            for (int nj = 0; nj < 4; nj++) {
                int n0 = warp_n + nj * 8 + (l & 3) * 2;
                float v0 = fmaxf(fmaf(acc[mi][nj][half * 2 + 0], sc[nj][0], sh[nj][0]), 0.f);
                float v1 = fmaxf(fmaf(acc[mi][nj][half * 2 + 1], sc[nj][1], sh[nj][1]), 0.f);
                *(float2*)&g_merge[(long)m * 128 + n0] = make_float2(v0, v1);
            }
        }
}

// ============================================================================
// k5: attention logits, wa1 cached in smem.  grid 1296, block 256
// ============================================================================
__global__ __launch_bounds__(256) void k5_logits(
    const float* __restrict__ wa1, const float* __restrict__ ba1,
    const float* __restrict__ bna, const float* __restrict__ wa2,
    const float* __restrict__ ba2)
{
    __shared__ float wa1s[64][129];
    __shared__ float xs[4][128];
    __shared__ float wa2s[64];
    __shared__ float bnsc[64], bnsh[64];
    __shared__ float red[8];
    const int tid = threadIdx.x;
    const int m0 = blockIdx.x * 16;
    const int o  = tid & 63;
    const int mi = tid >> 6;

    for (int i = tid; i < 64 * 128; i += 256)
        wa1s[i >> 7][i & 127] = wa1[i];
    if (tid < 64) {
        float g = bna[tid], be = bna[64 + tid], mu = bna[128 + tid], va = bna[192 + tid];
        float s = g * rsqrtf(va + EPSV);
        bnsc[tid] = s;
        bnsh[tid] = (ba1[tid] - mu) * s + be;
        wa2s[tid] = wa2[tid];
    }
    const float ba2v = ba2[0];
    __syncthreads();

    for (int it = 0; it < 4; it++) {
        {
            int i = tid;
            xs[i >> 7][i & 127] = g_x2f[(long)(m0 + it * 4 + (i >> 7)) * 128 + (i & 127)];
            i += 256;
            xs[i >> 7][i & 127] = g_x2f[(long)(m0 + it * 4 + (i >> 7)) * 128 + (i & 127)];
        }
        __syncthreads();
        float acc = 0.f;
#pragma unroll 8
        for (int c = 0; c < 128; c++) acc = fmaf(wa1s[o][c], xs[mi][c], acc);
        float t = fmaxf(fmaf(acc, bnsc[o], bnsh[o]), 0.f);
        float p = wa2s[o] * t;
#pragma unroll
        for (int off = 16; off > 0; off >>= 1) p += __shfl_down_sync(0xffffffffu, p, off);
        if ((tid & 31) == 0) red[tid >> 5] = p;
        __syncthreads();
        if (o == 0) g_logits[m0 + it * 4 + mi] = red[mi * 2] + red[mi * 2 + 1] + ba2v;
        __syncthreads();
    }
}

// ============================================================================
// k6: softmax(81) + attention-pool + final linear (128->6).  grid 256, block 128
// ============================================================================
__global__ __launch_bounds__(128) void k6_final(
    const float* __restrict__ wl, const float* __restrict__ bl,
    float* __restrict__ out)
{
    __shared__ float att[81];
    __shared__ float pooled[128];
    __shared__ float red[4];
    const int b = blockIdx.x;
    const int t = threadIdx.x;

    float v = (t < 81) ? g_logits[b * 81 + t] : -1e30f;
    float mx = v;
#pragma unroll
    for (int off = 16; off > 0; off >>= 1) mx = fmaxf(mx, __shfl_xor_sync(0xffffffffu, mx, off));
    if ((t & 31) == 0) red[t >> 5] = mx;
    __syncthreads();
    mx = fmaxf(fmaxf(red[0], red[1]), fmaxf(red[2], red[3]));
    float e = (t < 81) ? expf(v - mx) : 0.f;
    __syncthreads();
    float sm = e;
#pragma unroll
    for (int off = 16; off > 0; off >>= 1) sm += __shfl_xor_sync(0xffffffffu, sm, off);
    if ((t & 31) == 0) red[t >> 5] = sm;
    __syncthreads();
    sm = red[0] + red[1] + red[2] + red[3];
    if (t < 81) att[t] = e / sm;
    __syncthreads();

    float acc = 0.f;
    const float* mr = g_merge + (long)b * 81 * 128 + t;
#pragma unroll 9
    for (int p = 0; p < 81; p++) acc = fmaf(att[p], mr[p * 128], acc);
    pooled[t] = acc;
    __syncthreads();

    if (t < 6) {
        float s2 = bl[t];
        const float* wr = wl + t * 128;
#pragma unroll 8
        for (int o = 0; o < 128; o++) s2 = fmaf(wr[o], pooled[o], s2);
        out[b * 6 + t] = s2;
    }
}

// ============================================================================
extern "C" void kernel_launch(void* const* d_in, const int* in_sizes, int n_in,
                              void* d_out, int out_size)
{
    const float* x    = (const float*)d_in[0];
    const float* w1   = (const float*)d_in[1];
    const float* b1   = (const float*)d_in[2];
    const float* bn1  = (const float*)d_in[3];
    const float* w2   = (const float*)d_in[4];
    const float* b2   = (const float*)d_in[5];
    const float* bn2  = (const float*)d_in[6];
    const float* wgt  = (const float*)d_in[7];
    const float* w3   = (const float*)d_in[8];
    const float* b3   = (const float*)d_in[9];
    const float* bn3  = (const float*)d_in[10];
    const float* w4   = (const float*)d_in[11];
    const float* b4   = (const float*)d_in[12];
    const float* bn4  = (const float*)d_in[13];
    const float* wa1  = (const float*)d_in[14];
    const float* ba1  = (const float*)d_in[15];
    const float* bna  = (const float*)d_in[16];
    const float* wa2  = (const float*)d_in[17];
    const float* ba2  = (const float*)d_in[18];
    const float* wl   = (const float*)d_in[19];
    const float* bl   = (const float*)d_in[20];
    float* out = (float*)d_out;

    cudaFuncSetAttribute(k1_mma, cudaFuncAttributeMaxDynamicSharedMemorySize, K1_SMEM);
    cudaFuncSetAttribute(k2_mma, cudaFuncAttributeMaxDynamicSharedMemorySize, K2_SMEM);
    cudaFuncSetAttribute(k3_mma, cudaFuncAttributeMaxDynamicSharedMemorySize, K3_SMEM);
    cudaFuncSetAttribute(k4_mma, cudaFuncAttributeMaxDynamicSharedMemorySize, K4_SMEM);

    // launch order keeps k2_mma in ncu's sampled slot (4th launch)
    prepA<<<30848, 256>>>(x, w1);                  // 1
    dim3 g1(225, 2);
    k1_mma<<<g1, 256, K1_SMEM>>>(b1, bn1);         // 2
    prepB<<<4568, 256>>>(w2, w3, w4, wgt);         // 3
    k2_mma<<<162, 256, K2_SMEM>>>(b2, bn2);        // 4  <-- profiled
    k3_mma<<<162, 256, K3_SMEM>>>(b3, bn3);        // 5
    k4_mma<<<162, 256, K4_SMEM>>>(b4, bn4);        // 6
    k5_logits<<<1296, 256>>>(wa1, ba1, bna, wa2, ba2); // 7
    k6_final<<<256, 128>>>(wl, bl, out);           // 8
}

// round 14
// speedup vs baseline: 1.2139x; 1.2139x over previous
#include <cuda_runtime.h>
#include <cuda_bf16.h>
#include <cstdint>

#define EPSV 1e-5f

typedef unsigned long long ull;

// ---------------- scratch buffers (static, allocation-free) ----------------
__device__ __nv_bfloat16 g_xth[225 * 256 * 256]; // x transposed+split: [ij][m][ck<=255]
__device__ __nv_bfloat16 g_xtl[225 * 256 * 256];
__device__ __nv_bfloat16 g_B1h[225 * 128 * 256]; // per-ij conv1 B matrices, split
__device__ __nv_bfloat16 g_B1l[225 * 128 * 256];
__device__ __nv_bfloat16 g_y1h[256 * 225 * 128]; // y1 split, ch-last (m, sp, c)
__device__ __nv_bfloat16 g_y1l[256 * 225 * 128];
__device__ __nv_bfloat16 g_w2h[128 * 6272];      // w2 split: [n][(kh*7+kw)*128+ci]
__device__ __nv_bfloat16 g_w2l[128 * 6272];
__device__ float         g_x2f[20736 * 128];     // x_ fp32 ch-last [m][c] (for k5)
__device__ __nv_bfloat16 g_a3h[20736 * 144];     // k3 A operand split: [m][144]
__device__ __nv_bfloat16 g_a3l[20736 * 144];
__device__ __nv_bfloat16 g_w3h[128 * 144];
__device__ __nv_bfloat16 g_w3l[128 * 144];
__device__ __nv_bfloat16 g_y3h[20736 * 128];
__device__ __nv_bfloat16 g_y3l[20736 * 128];
__device__ __nv_bfloat16 g_w4h[128 * 128];
__device__ __nv_bfloat16 g_w4l[128 * 128];
__device__ float         g_merge[20736 * 128];   // fp32 ch-last [m][c]
__device__ float         g_logits[20736];

// ---------------- PTX helpers (baseline sm_80+) ----------------
__device__ __forceinline__ uint32_t smem_u32(const void* p) {
    uint32_t a;
    asm("{ .reg .u64 t; cvta.to.shared.u64 t, %1; cvt.u32.u64 %0, t; }" : "=r"(a) : "l"(p));
    return a;
}
__device__ __forceinline__ void cpa16(uint32_t dst, const void* src) {
    asm volatile("cp.async.ca.shared.global [%0], [%1], 16;" :: "r"(dst), "l"(src));
}
#define CP_COMMIT() asm volatile("cp.async.commit_group;" ::: "memory")
#define CP_WAIT2()  asm volatile("cp.async.wait_group 2;" ::: "memory")
#define CP_WAIT1()  asm volatile("cp.async.wait_group 1;" ::: "memory")
#define CP_WAIT0()  asm volatile("cp.async.wait_group 0;" ::: "memory")

__device__ __forceinline__ void ldsm4(uint32_t* r, uint32_t addr) {
    asm volatile("ldmatrix.sync.aligned.m8n8.x4.shared.b16 {%0,%1,%2,%3}, [%4];"
                 : "=r"(r[0]), "=r"(r[1]), "=r"(r[2]), "=r"(r[3]) : "r"(addr));
}
__device__ __forceinline__ void mma16816(float* d, const uint32_t* a, const uint32_t* b) {
    asm volatile(
        "mma.sync.aligned.m16n8k16.row.col.f32.bf16.bf16.f32 "
        "{%0,%1,%2,%3}, {%4,%5,%6,%7}, {%8,%9}, {%0,%1,%2,%3};"
        : "+f"(d[0]), "+f"(d[1]), "+f"(d[2]), "+f"(d[3])
        : "r"(a[0]), "r"(a[1]), "r"(a[2]), "r"(a[3]), "r"(b[0]), "r"(b[1]));
}
__device__ __forceinline__ uint32_t cvt2(float f0, float f1) {
    uint32_t r;
    asm("cvt.rn.bf16x2.f32 %0, %1, %2;" : "=r"(r) : "f"(f1), "f"(f0));
    return r;
}
__device__ __forceinline__ void split2(float v0, float v1, uint32_t& h, uint32_t& lo) {
    h = cvt2(v0, v1);
    float r0 = v0 - __uint_as_float(h << 16);
    float r1 = v1 - __uint_as_float(h & 0xFFFF0000u);
    lo = cvt2(r0, r1);
}

// ============================================================================
// prepA: merged kX (x transpose+split) + kB (per-ij B1 matrices)
// ============================================================================
__global__ __launch_bounds__(256) void prepA(const float* __restrict__ x,
                                             const float* __restrict__ w1)
{
    const int b = blockIdx.x;
    if (b < 2048) {
        __shared__ float s[225][33];
        const int tid = threadIdx.x;
        const int tx = tid & 31, ty = tid >> 5;
        const int ij0 = (b & 7) * 32;
        const int m   = b >> 3;
        const int nij = (ij0 + 32 <= 225) ? 32 : (225 - ij0);

        const float* xp = x + (long)m * 50625;
        for (int cc = 0; cc < 29; cc++) {
            int c = cc * 8 + ty;
            if (c < 225) {
                float v = (tx < nij) ? xp[c * 225 + ij0 + tx] : 0.f;
                s[c][tx] = v;
            }
        }
        __syncthreads();
        for (int ii = 0; ii < nij; ii++) {
            float v = (tid < 225) ? s[tid][ii] : 0.f;
            __nv_bfloat16 h = __float2bfloat16(v);
            long idx = ((long)(ij0 + ii) * 256 + m) * 256 + tid;
            g_xth[idx] = h;
            g_xtl[idx] = __float2bfloat16(v - __bfloat162float(h));
        }
    } else {
        const int bid = b - 2048;
        const int ij = bid >> 7, n = bid & 127;
        const int ip = ij / 15, jp = ij - ip * 15;
        const int k = threadIdx.x;
        float v = 0.f;
        if (k < 225) {
            int a = k / 15, bb = k - a * 15;
            v = w1[n * 841 + (a + 14 - ip) * 29 + (bb + 14 - jp)];
        }
        __nv_bfloat16 h = __float2bfloat16(v);
        long idx = ((long)ij * 128 + n) * 256 + k;
        g_B1h[idx] = h;
        g_B1l[idx] = __float2bfloat16(v - __bfloat162float(h));
    }
}

// ============================================================================
// prepB: merged kT2 + kT3 + kT4 + kF.  grid 4568, block 256
// ============================================================================
__global__ __launch_bounds__(256) void prepB(const float* __restrict__ w2,
                                             const float* __restrict__ w3,
                                             const float* __restrict__ w4,
                                             const float* __restrict__ wgt)
{
    const int b = blockIdx.x;
    if (b < 3136) {
        int t = b * 256 + threadIdx.x;
        if (t < 128 * 6272) {
            int n = t / 6272, k = t - n * 6272;
            int g = k >> 7, ci = k & 127;
            float v = w2[n * 6272 + ci * 49 + g];
            __nv_bfloat16 h = __float2bfloat16(v);
            g_w2h[t] = h;
            g_w2l[t] = __float2bfloat16(v - __bfloat162float(h));
        }
    } else if (b < 3136 + 72) {
        int t = (b - 3136) * 256 + threadIdx.x;
        if (t < 128 * 144) {
            int n = t / 144, j = t - n * 144;
            float v = 0.f;
            if (j < 5)                  v = w3[n * 133 + j];
            else if (j >= 8 && j < 136) v = w3[n * 133 + j - 3];
            __nv_bfloat16 h = __float2bfloat16(v);
            g_w3h[t] = h;
            g_w3l[t] = __float2bfloat16(v - __bfloat162float(h));
        }
    } else if (b < 3136 + 72 + 64) {
        int t = (b - 3136 - 72) * 256 + threadIdx.x;
        if (t < 128 * 128) {
            float v = w4[t];
            __nv_bfloat16 h = __float2bfloat16(v);
            g_w4h[t] = h;
            g_w4l[t] = __float2bfloat16(v - __bfloat162float(h));
        }
    } else {
        int t = (b - 3136 - 72 - 64) * 256 + threadIdx.x;
        if (t < 20736 * 16) {
            int m = t >> 4, jj = t & 15;
            int j = (jj < 8) ? jj : (128 + jj);
            float v = (j < 5) ? wgt[j * 81 + (m % 81)] : 0.f;
            __nv_bfloat16 h = __float2bfloat16(v);
            long idx = (long)m * 144 + j;
            g_a3h[idx] = h;
            g_a3l[idx] = __float2bfloat16(v - __bfloat162float(h));
        }
    }
}

// ============================================================================
// k1: align-conv1 as MMA (R9-proven).  per ij: M=256, N=128, K=256(padded).
// grid (225, 2), block 256.  4 stages KT=64, double-buffered, 147KB.
// ============================================================================
#define LDA1    144
#define T1PLANE (128 * 144)
#define STAGE1  (4 * T1PLANE)
#define K1_SMEM (2 * STAGE1)       // 147456

__global__ __launch_bounds__(256) void k1_mma(
    const float* __restrict__ b1, const float* __restrict__ bn1)
{
    extern __shared__ char smem[];
    const uint32_t sb = smem_u32(smem);
    const int tid = threadIdx.x;
    const int w = tid >> 5, l = tid & 31;
    const int ij = blockIdx.x;
    const int m0 = blockIdx.y * 128;
    const int warp_m = (w >> 2) * 64;
    const int warp_n = (w & 3) * 32;

    const int row = tid & 127, ver = tid >> 7;
    const __nv_bfloat16* asrc = (ver ? g_xtl : g_xth) + ((long)ij * 256 + m0 + row) * 256;
    const __nv_bfloat16* bsrc = (ver ? g_B1l : g_B1h) + ((long)ij * 128 + row) * 256;
    const uint32_t dA = sb + ver * T1PLANE + row * LDA1;
    const uint32_t dB = sb + 2 * T1PLANE + ver * T1PLANE + row * LDA1;

    float acc[4][4][4];
#pragma unroll
    for (int i = 0; i < 4; i++)
#pragma unroll
        for (int j = 0; j < 4; j++)
#pragma unroll
            for (int c = 0; c < 4; c++) acc[i][j][c] = 0.f;

    auto load_stage = [&](int s, uint32_t off) {
#pragma unroll
        for (int j = 0; j < 8; j++) {
            cpa16(dA + off + j * 16, asrc + s * 64 + j * 8);
            cpa16(dB + off + j * 16, bsrc + s * 64 + j * 8);
        }
    };

    const uint32_t aAddrM = (warp_m + (l & 15)) * LDA1 + ((l >> 4) << 4);
    const uint32_t bAddrN = (warp_n + (l & 7) + ((l >> 4) << 3)) * LDA1 + (((l >> 3) & 1) << 4);
    auto compute_stage = [&](uint32_t off) {
        uint32_t base = sb + off;
#pragma unroll
        for (int ks = 0; ks < 4; ks++) {
            uint32_t ko = ks * 32;
            uint32_t ah[4][4], al[4][4];
#pragma unroll
            for (int mi = 0; mi < 4; mi++) {
                uint32_t ad = base + aAddrM + mi * (16 * LDA1) + ko;
                ldsm4(ah[mi], ad);
                ldsm4(al[mi], ad + T1PLANE);
            }
            uint32_t bh[2][4], bl[2][4];
#pragma unroll
            for (int nb = 0; nb < 2; nb++) {
                uint32_t bd = base + 2 * T1PLANE + bAddrN + nb * (16 * LDA1) + ko;
                ldsm4(bh[nb], bd);
                ldsm4(bl[nb], bd + T1PLANE);
            }
#pragma unroll
            for (int mi = 0; mi < 4; mi++)
#pragma unroll
                for (int nj = 0; nj < 4; nj++)
                    mma16816(acc[mi][nj], ah[mi], &bh[nj >> 1][(nj & 1) * 2]);
#pragma unroll
            for (int mi = 0; mi < 4; mi++)
#pragma unroll
                for (int nj = 0; nj < 4; nj++)
                    mma16816(acc[mi][nj], ah[mi], &bl[nj >> 1][(nj & 1) * 2]);
#pragma unroll
            for (int mi = 0; mi < 4; mi++)
#pragma unroll
                for (int nj = 0; nj < 4; nj++)
                    mma16816(acc[mi][nj], al[mi], &bh[nj >> 1][(nj & 1) * 2]);
        }
    };

    load_stage(0, 0);
    CP_COMMIT();
    for (int s = 0; s < 4; s++) {
        if (s + 1 < 4) load_stage(s + 1, ((s + 1) & 1) * STAGE1);
        CP_COMMIT();
        CP_WAIT1();
        __syncthreads();
        compute_stage((s & 1) * STAGE1);
        __syncthreads();
    }

    float sc[4][2], sh[4][2];
#pragma unroll
    for (int nj = 0; nj < 4; nj++)
#pragma unroll
        for (int q = 0; q < 2; q++) {
            int n = warp_n + nj * 8 + (l & 3) * 2 + q;
            float g = bn1[n], be = bn1[128 + n], mu = bn1[256 + n], va = bn1[384 + n];
            float s = g * rsqrtf(va + EPSV);
            sc[nj][q] = s;
            sh[nj][q] = (b1[n] - mu) * s + be;
        }
#pragma unroll
    for (int mi = 0; mi < 4; mi++)
#pragma unroll
        for (int half = 0; half < 2; half++) {
            int m = m0 + warp_m + mi * 16 + (l >> 2) + half * 8;
            long base = ((long)m * 225 + ij) * 128;
#pragma unroll
            for (int nj = 0; nj < 4; nj++) {
                int n0 = warp_n + nj * 8 + (l & 3) * 2;
                float v0 = fmaxf(fmaf(acc[mi][nj][half * 2 + 0], sc[nj][0], sh[nj][0]), 0.f);
                float v1 = fmaxf(fmaf(acc[mi][nj][half * 2 + 1], sc[nj][1], sh[nj][1]), 0.f);
                uint32_t h, lo;
                split2(v0, v1, h, lo);
                *(uint32_t*)&g_y1h[base + n0] = h;
                *(uint32_t*)&g_y1l[base + n0] = lo;
            }
        }
}

// ============================================================================
// k2: 7x7 conv MMA, M=20736 N=128 K=6272.  M-TILE 144 -> grid 144 = ONE WAVE.
// block 288 (9 warps, warp tile 16x128), 4-stage cp.async ring (170KB).
// ============================================================================
#define LDA    80
#define A2_V   (144 * 80)          // 11520
#define B2_V   (128 * 80)          // 10240
#define STG2   (2 * A2_V + 2 * B2_V)   // 43520
#define K2_SMEM (4 * STG2)         // 174080

__global__ __launch_bounds__(288, 1) void k2_mma(
    const float* __restrict__ b2, const float* __restrict__ bn2)
{
    extern __shared__ char smem[];
    const uint32_t sb = smem_u32(smem);
    const int tid = threadIdx.x;
    const int w = tid >> 5, l = tid & 31;   // 9 warps
    const int m0 = blockIdx.x * 144;

    // ---- A loader: 144 rows x 2 chunks = 288 threads ----
    const int ar = tid >> 1;
    const int ac = (tid & 1) * 32;
    const int ae = ac >> 1;
    const int gm = m0 + ar;
    const int bv = gm / 81;
    const int pos = gm - bv * 81;
    const int oh = pos / 9, ow = pos - oh * 9;
    const long a_base = ((long)bv * 225 + oh * 15 + ow) * 128;
    const uint32_t dstA = sb + ar * LDA + ac;
    // ---- B loader: threads 0..255, 128 rows x 2 chunks ----
    const int br = (tid < 256) ? (tid >> 1) : 0;
    const __nv_bfloat16* wh_src = g_w2h + (long)br * 6272;
    const __nv_bfloat16* wl_src = g_w2l + (long)br * 6272;
    const uint32_t dstB = sb + 2 * A2_V + br * LDA + ac;

    float acc[16][4];
#pragma unroll
    for (int i = 0; i < 16; i++)
#pragma unroll
        for (int c = 0; c < 4; c++) acc[i][c] = 0.f;

    auto load_stage = [&](int s, uint32_t off) {
        int g  = s >> 2;
        int kh = g / 7, kw = g - kh * 7;
        long aoff = a_base + (kh * 15 + kw) * 128 + (s & 3) * 32 + ae;
        const __nv_bfloat16* pah = g_y1h + aoff;
        const __nv_bfloat16* pal = g_y1l + aoff;
        uint32_t dA = dstA + off;
        cpa16(dA, pah);
        cpa16(dA + 16, pah + 8);
        cpa16(dA + A2_V, pal);
        cpa16(dA + A2_V + 16, pal + 8);
        if (tid < 256) {
            long boff = (long)s * 32 + ae;
            uint32_t dB = dstB + off;
            cpa16(dB, wh_src + boff);
            cpa16(dB + 16, wh_src + boff + 8);
            cpa16(dB + B2_V, wl_src + boff);
            cpa16(dB + B2_V + 16, wl_src + boff + 8);
        }
    };

    const uint32_t aAddrM = (w * 16 + (l & 15)) * LDA + ((l >> 4) << 4);
    const uint32_t bAddrN = ((l & 7) + ((l >> 4) << 3)) * LDA + (((l >> 3) & 1) << 4);
    auto compute_stage = [&](uint32_t off) {
        uint32_t base = sb + off;
#pragma unroll
        for (int ks = 0; ks < 2; ks++) {
            uint32_t ko = ks * 32;
            uint32_t ah[4], al[4];
            {
                uint32_t ad = base + aAddrM + ko;
                ldsm4(ah, ad);
                ldsm4(al, ad + A2_V);
            }
            uint32_t bh[8][4], bl[8][4];
#pragma unroll
            for (int nb = 0; nb < 8; nb++) {
                uint32_t bd = base + 2 * A2_V + bAddrN + nb * (16 * LDA) + ko;
                ldsm4(bh[nb], bd);
                ldsm4(bl[nb], bd + B2_V);
            }
#pragma unroll
            for (int nj = 0; nj < 16; nj++)
                mma16816(acc[nj], ah, &bh[nj >> 1][(nj & 1) * 2]);
#pragma unroll
            for (int nj = 0; nj < 16; nj++)
                mma16816(acc[nj], ah, &bl[nj >> 1][(nj & 1) * 2]);
#pragma unroll
            for (int nj = 0; nj < 16; nj++)
                mma16816(acc[nj], al, &bh[nj >> 1][(nj & 1) * 2]);
        }
    };

    // ---- 4-deep pipeline ----
    load_stage(0, 0);            CP_COMMIT();
    load_stage(1, STG2);         CP_COMMIT();
    load_stage(2, 2 * STG2);     CP_COMMIT();
    for (int s = 0; s < 196; s++) {
        CP_WAIT2();
        __syncthreads();
        compute_stage((s & 3) * STG2);
        if (s + 3 < 196) load_stage(s + 3, ((s + 3) & 3) * STG2);
        CP_COMMIT();
    }

    // ---- epilogue ----
    float sc[16][2], sh[16][2];
#pragma unroll
    for (int nj = 0; nj < 16; nj++)
#pragma unroll
        for (int q = 0; q < 2; q++) {
            int n = nj * 8 + (l & 3) * 2 + q;
            float g = bn2[n], be = bn2[128 + n], mu = bn2[256 + n], va = bn2[384 + n];
            float s = g * rsqrtf(va + EPSV);
            sc[nj][q] = s;
            sh[nj][q] = (b2[n] - mu) * s + be;
        }
#pragma unroll
    for (int half = 0; half < 2; half++) {
        int m = m0 + w * 16 + (l >> 2) + half * 8;
#pragma unroll
        for (int nj = 0; nj < 16; nj++) {
            int n0 = nj * 8 + (l & 3) * 2;
            float v0 = fmaxf(fmaf(acc[nj][half * 2 + 0], sc[nj][0], sh[nj][0]), 0.f);
            float v1 = fmaxf(fmaf(acc[nj][half * 2 + 1], sc[nj][1], sh[nj][1]), 0.f);
            *(float2*)&g_x2f[(long)m * 128 + n0] = make_float2(v0, v1);
            uint32_t h, lo;
            split2(v0, v1, h, lo);
            *(uint32_t*)&g_a3h[(long)m * 144 + 8 + n0] = h;
            *(uint32_t*)&g_a3l[(long)m * 144 + 8 + n0] = lo;
        }
    }
}

// ============================================================================
// k3: conv1x1 144->128 MMA (monolithic smem), grid 162, block 256
// ============================================================================
#define LDA3    304
#define T3PLANE (128 * 304)
#define K3_SMEM (4 * T3PLANE)

__global__ __launch_bounds__(256) void k3_mma(
    const float* __restrict__ b3, const float* __restrict__ bn3)
{
    extern __shared__ char smem[];
    const uint32_t sb = smem_u32(smem);
    const int tid = threadIdx.x;
    const int w = tid >> 5, l = tid & 31;
    const int m0 = blockIdx.x * 128;
    const int warp_m = (w >> 2) * 64;
    const int warp_n = (w & 3) * 32;

    const int row = tid & 127, ver = tid >> 7;
    const __nv_bfloat16* asrc = (ver ? g_a3l : g_a3h) + (long)(m0 + row) * 144;
    const __nv_bfloat16* bsrc = (ver ? g_w3l : g_w3h) + row * 144;
    const uint32_t dA = sb + ver * T3PLANE + row * LDA3;
    const uint32_t dB = sb + 2 * T3PLANE + ver * T3PLANE + row * LDA3;
#pragma unroll
    for (int j = 0; j < 18; j++) {
        cpa16(dA + j * 16, asrc + j * 8);
        cpa16(dB + j * 16, bsrc + j * 8);
    }
    CP_COMMIT();

    float acc[4][4][4];
#pragma unroll
    for (int i = 0; i < 4; i++)
#pragma unroll
        for (int j = 0; j < 4; j++)
#pragma unroll
            for (int c = 0; c < 4; c++) acc[i][j][c] = 0.f;

    CP_WAIT0();
    __syncthreads();

    const uint32_t aAddrM = (warp_m + (l & 15)) * LDA3 + ((l >> 4) << 4);
    const uint32_t bAddrN = (warp_n + (l & 7) + ((l >> 4) << 3)) * LDA3 + (((l >> 3) & 1) << 4);
#pragma unroll
    for (int ks = 0; ks < 9; ks++) {
        uint32_t ko = ks * 32;
        uint32_t ah[4][4], al[4][4];
#pragma unroll
        for (int mi = 0; mi < 4; mi++) {
            uint32_t ad = sb + aAddrM + mi * (16 * LDA3) + ko;
            ldsm4(ah[mi], ad);
            ldsm4(al[mi], ad + T3PLANE);
        }
        uint32_t bh[2][4], bl[2][4];
#pragma unroll
        for (int nb = 0; nb < 2; nb++) {
            uint32_t bd = sb + 2 * T3PLANE + bAddrN + nb * (16 * LDA3) + ko;
            ldsm4(bh[nb], bd);
            ldsm4(bl[nb], bd + T3PLANE);
        }
#pragma unroll
        for (int mi = 0; mi < 4; mi++)
#pragma unroll
            for (int nj = 0; nj < 4; nj++)
                mma16816(acc[mi][nj], ah[mi], &bh[nj >> 1][(nj & 1) * 2]);
#pragma unroll
        for (int mi = 0; mi < 4; mi++)
#pragma unroll
            for (int nj = 0; nj < 4; nj++)
                mma16816(acc[mi][nj], ah[mi], &bl[nj >> 1][(nj & 1) * 2]);
#pragma unroll
        for (int mi = 0; mi < 4; mi++)
#pragma unroll
            for (int nj = 0; nj < 4; nj++)
                mma16816(acc[mi][nj], al[mi], &bh[nj >> 1][(nj & 1) * 2]);
    }

    float sc[4][2], sh[4][2];
#pragma unroll
    for (int nj = 0; nj < 4; nj++)
#pragma unroll
        for (int q = 0; q < 2; q++) {
            int n = warp_n + nj * 8 + (l & 3) * 2 + q;
            float g = bn3[n], be = bn3[128 + n], mu = bn3[256 + n], va = bn3[384 + n];
            float s = g * rsqrtf(va + EPSV);
            sc[nj][q] = s;
            sh[nj][q] = (b3[n] - mu) * s + be;
        }
#pragma unroll
    for (int mi = 0; mi < 4; mi++)
#pragma unroll
        for (int half = 0; half < 2; half++) {
            int m = m0 + warp_m + mi * 16 + (l >> 2) + half * 8;
#pragma unroll
            for (int nj = 0; nj < 4; nj++) {
                int n0 = warp_n + nj * 8 + (l & 3) * 2;
                float v0 = fmaxf(fmaf(acc[mi][nj][half * 2 + 0], sc[nj][0], sh[nj][0]), 0.f);
                float v1 = fmaxf(fmaf(acc[mi][nj][half * 2 + 1], sc[nj][1], sh[nj][1]), 0.f);
                uint32_t h, lo;
                split2(v0, v1, h, lo);
                *(uint32_t*)&g_y3h[(long)m * 128 + n0] = h;
                *(uint32_t*)&g_y3l[(long)m * 128 + n0] = lo;
            }
        }
}

// ============================================================================
// k4: conv1x1 128->128 MMA (monolithic smem) -> g_merge fp32 ch-last
// ============================================================================
#define LDA4    272
#define T4PLANE (128 * 272)
#define K4_SMEM (4 * T4PLANE)

__global__ __launch_bounds__(256) void k4_mma(
    const float* __restrict__ b4, const float* __restrict__ bn4)
{
    extern __shared__ char smem[];
    const uint32_t sb = smem_u32(smem);
    const int tid = threadIdx.x;
    const int w = tid >> 5, l = tid & 31;
    const int m0 = blockIdx.x * 128;
    const int warp_m = (w >> 2) * 64;
    const int warp_n = (w & 3) * 32;

    const int row = tid & 127, ver = tid >> 7;
    const __nv_bfloat16* asrc = (ver ? g_y3l : g_y3h) + (long)(m0 + row) * 128;
    const __nv_bfloat16* bsrc = (ver ? g_w4l : g_w4h) + row * 128;
    const uint32_t dA = sb + ver * T4PLANE + row * LDA4;
    const uint32_t dB = sb + 2 * T4PLANE + ver * T4PLANE + row * LDA4;
#pragma unroll
    for (int j = 0; j < 16; j++) {
        cpa16(dA + j * 16, asrc + j * 8);
        cpa16(dB + j * 16, bsrc + j * 8);
    }
    CP_COMMIT();

    float acc[4][4][4];
#pragma unroll
    for (int i = 0; i < 4; i++)
#pragma unroll
        for (int j = 0; j < 4; j++)
#pragma unroll
            for (int c = 0; c < 4; c++) acc[i][j][c] = 0.f;

    CP_WAIT0();
    __syncthreads();

    const uint32_t aAddrM = (warp_m + (l & 15)) * LDA4 + ((l >> 4) << 4);
    const uint32_t bAddrN = (warp_n + (l & 7) + ((l >> 4) << 3)) * LDA4 + (((l >> 3) & 1) << 4);
#pragma unroll
    for (int ks = 0; ks < 8; ks++) {
        uint32_t ko = ks * 32;
        uint32_t ah[4][4], al[4][4];
#pragma unroll
        for (int mi = 0; mi < 4; mi++) {
            uint32_t ad = sb + aAddrM + mi * (16 * LDA4) + ko;
            ldsm4(ah[mi], ad);
            ldsm4(al[mi], ad + T4PLANE);
        }
        uint32_t bh[2][4], bl[2][4];
#pragma unroll
        for (int nb = 0; nb < 2; nb++) {
            uint32_t bd = sb + 2 * T4PLANE + bAddrN + nb * (16 * LDA4) + ko;
            ldsm4(bh[nb], bd);
            ldsm4(bl[nb], bd + T4PLANE);
        }
#pragma unroll
        for (int mi = 0; mi < 4; mi++)
#pragma unroll
            for (int nj = 0; nj < 4; nj++)
                mma16816(acc[mi][nj], ah[mi], &bh[nj >> 1][(nj & 1) * 2]);
#pragma unroll
        for (int mi = 0; mi < 4; mi++)
#pragma unroll
            for (int nj = 0; nj < 4; nj++)
                mma16816(acc[mi][nj], ah[mi], &bl[nj >> 1][(nj & 1) * 2]);
#pragma unroll
        for (int mi = 0; mi < 4; mi++)
#pragma unroll
            for (int nj = 0; nj < 4; nj++)
                mma16816(acc[mi][nj], al[mi], &bh[nj >> 1][(nj & 1) * 2]);
    }

    float sc[4][2], sh[4][2];
#pragma unroll
    for (int nj = 0; nj < 4; nj++)
#pragma unroll
        for (int q = 0; q < 2; q++) {
            int n = warp_n + nj * 8 + (l & 3) * 2 + q;
            float g = bn4[n], be = bn4[128 + n], mu = bn4[256 + n], va = bn4[384 + n];
            float s = g * rsqrtf(va + EPSV);
            sc[nj][q] = s;
            sh[nj][q] = (b4[n] - mu) * s + be;
        }
#pragma unroll
    for (int mi = 0; mi < 4; mi++)
#pragma unroll
        for (int half = 0; half < 2; half++) {
            int m = m0 + warp_m + mi * 16 + (l >> 2) + half * 8;
#pragma unroll
            for (int nj = 0; nj < 4; nj++) {
                int n0 = warp_n + nj * 8 + (l & 3) * 2;
                float v0 = fmaxf(fmaf(acc[mi][nj][half * 2 + 0], sc[nj][0], sh[nj][0]), 0.f);
                float v1 = fmaxf(fmaf(acc[mi][nj][half * 2 + 1], sc[nj][1], sh[nj][1]), 0.f);
                *(float2*)&g_merge[(long)m * 128 + n0] = make_float2(v0, v1);
            }
        }
}

// ============================================================================
// k5: attention logits, wa1 cached in smem.  grid 1296, block 256
// ============================================================================
__global__ __launch_bounds__(256) void k5_logits(
    const float* __restrict__ wa1, const float* __restrict__ ba1,
    const float* __restrict__ bna, const float* __restrict__ wa2,
    const float* __restrict__ ba2)
{
    __shared__ float wa1s[64][129];
    __shared__ float xs[4][128];
    __shared__ float wa2s[64];
    __shared__ float bnsc[64], bnsh[64];
    __shared__ float red[8];
    const int tid = threadIdx.x;
    const int m0 = blockIdx.x * 16;
    const int o  = tid & 63;
    const int mi = tid >> 6;

    for (int i = tid; i < 64 * 128; i += 256)
        wa1s[i >> 7][i & 127] = wa1[i];
    if (tid < 64) {
        float g = bna[tid], be = bna[64 + tid], mu = bna[128 + tid], va = bna[192 + tid];
        float s = g * rsqrtf(va + EPSV);
        bnsc[tid] = s;
        bnsh[tid] = (ba1[tid] - mu) * s + be;
        wa2s[tid] = wa2[tid];
    }
    const float ba2v = ba2[0];
    __syncthreads();

    for (int it = 0; it < 4; it++) {
        {
            int i = tid;
            xs[i >> 7][i & 127] = g_x2f[(long)(m0 + it * 4 + (i >> 7)) * 128 + (i & 127)];
            i += 256;
            xs[i >> 7][i & 127] = g_x2f[(long)(m0 + it * 4 + (i >> 7)) * 128 + (i & 127)];
        }
        __syncthreads();
        float acc = 0.f;
#pragma unroll 8
        for (int c = 0; c < 128; c++) acc = fmaf(wa1s[o][c], xs[mi][c], acc);
        float t = fmaxf(fmaf(acc, bnsc[o], bnsh[o]), 0.f);
        float p = wa2s[o] * t;
#pragma unroll
        for (int off = 16; off > 0; off >>= 1) p += __shfl_down_sync(0xffffffffu, p, off);
        if ((tid & 31) == 0) red[tid >> 5] = p;
        __syncthreads();
        if (o == 0) g_logits[m0 + it * 4 + mi] = red[mi * 2] + red[mi * 2 + 1] + ba2v;
        __syncthreads();
    }
}

// ============================================================================
// k6: softmax(81) + attention-pool + final linear (128->6).  grid 256, block 128
// ============================================================================
__global__ __launch_bounds__(128) void k6_final(
    const float* __restrict__ wl, const float* __restrict__ bl,
    float* __restrict__ out)
{
    __shared__ float att[81];
    __shared__ float pooled[128];
    __shared__ float red[4];
    const int b = blockIdx.x;
    const int t = threadIdx.x;

    float v = (t < 81) ? g_logits[b * 81 + t] : -1e30f;
    float mx = v;
#pragma unroll
    for (int off = 16; off > 0; off >>= 1) mx = fmaxf(mx, __shfl_xor_sync(0xffffffffu, mx, off));
    if ((t & 31) == 0) red[t >> 5] = mx;
    __syncthreads();
    mx = fmaxf(fmaxf(red[0], red[1]), fmaxf(red[2], red[3]));
    float e = (t < 81) ? expf(v - mx) : 0.f;
    __syncthreads();
    float sm = e;
#pragma unroll
    for (int off = 16; off > 0; off >>= 1) sm += __shfl_xor_sync(0xffffffffu, sm, off);
    if ((t & 31) == 0) red[t >> 5] = sm;
    __syncthreads();
    sm = red[0] + red[1] + red[2] + red[3];
    if (t < 81) att[t] = e / sm;
    __syncthreads();

    float acc = 0.f;
    const float* mr = g_merge + (long)b * 81 * 128 + t;
#pragma unroll 9
    for (int p = 0; p < 81; p++) acc = fmaf(att[p], mr[p * 128], acc);
    pooled[t] = acc;
    __syncthreads();

    if (t < 6) {
        float s2 = bl[t];
        const float* wr = wl + t * 128;
#pragma unroll 8
        for (int o = 0; o < 128; o++) s2 = fmaf(wr[o], pooled[o], s2);
        out[b * 6 + t] = s2;
    }
}

// ============================================================================
extern "C" void kernel_launch(void* const* d_in, const int* in_sizes, int n_in,
                              void* d_out, int out_size)
{
    const float* x    = (const float*)d_in[0];
    const float* w1   = (const float*)d_in[1];
    const float* b1   = (const float*)d_in[2];
    const float* bn1  = (const float*)d_in[3];
    const float* w2   = (const float*)d_in[4];
    const float* b2   = (const float*)d_in[5];
    const float* bn2  = (const float*)d_in[6];
    const float* wgt  = (const float*)d_in[7];
    const float* w3   = (const float*)d_in[8];
    const float* b3   = (const float*)d_in[9];
    const float* bn3  = (const float*)d_in[10];
    const float* w4   = (const float*)d_in[11];
    const float* b4   = (const float*)d_in[12];
    const float* bn4  = (const float*)d_in[13];
    const float* wa1  = (const float*)d_in[14];
    const float* ba1  = (const float*)d_in[15];
    const float* bna  = (const float*)d_in[16];
    const float* wa2  = (const float*)d_in[17];
    const float* ba2  = (const float*)d_in[18];
    const float* wl   = (const float*)d_in[19];
    const float* bl   = (const float*)d_in[20];
    float* out = (float*)d_out;

    cudaFuncSetAttribute(k1_mma, cudaFuncAttributeMaxDynamicSharedMemorySize, K1_SMEM);
    cudaFuncSetAttribute(k2_mma, cudaFuncAttributeMaxDynamicSharedMemorySize, K2_SMEM);
    cudaFuncSetAttribute(k3_mma, cudaFuncAttributeMaxDynamicSharedMemorySize, K3_SMEM);
    cudaFuncSetAttribute(k4_mma, cudaFuncAttributeMaxDynamicSharedMemorySize, K4_SMEM);

    // launch order keeps k2_mma in ncu's sampled slot (4th launch)
    prepA<<<30848, 256>>>(x, w1);                  // 1
    dim3 g1(225, 2);
    k1_mma<<<g1, 256, K1_SMEM>>>(b1, bn1);         // 2
    prepB<<<4568, 256>>>(w2, w3, w4, wgt);         // 3
    k2_mma<<<144, 288, K2_SMEM>>>(b2, bn2);        // 4  <-- profiled, ONE wave
    k3_mma<<<162, 256, K3_SMEM>>>(b3, bn3);        // 5
    k4_mma<<<162, 256, K4_SMEM>>>(b4, bn4);        // 6
    k5_logits<<<1296, 256>>>(wa1, ba1, bna, wa2, ba2); // 7
    k6_final<<<256, 128>>>(wl, bl, out);           // 8
}

// round 15
// speedup vs baseline: 1.4999x; 1.2356x over previous
#include <cuda_runtime.h>
#include <cuda_bf16.h>
#include <cuda_fp16.h>
#include <cstdint>

#define EPSV 1e-5f

typedef unsigned long long ull;

// ---------------- scratch buffers (static, allocation-free) ----------------
__device__ __nv_bfloat16 g_xth[225 * 256 * 256]; // x transposed+split: [ij][m][ck<=255]
__device__ __nv_bfloat16 g_xtl[225 * 256 * 256];
__device__ __nv_bfloat16 g_B1h[225 * 128 * 256]; // per-ij conv1 B matrices, split
__device__ __nv_bfloat16 g_B1l[225 * 128 * 256];
__device__ __half        g_y1h[256 * 225 * 128]; // y1 fp16 split, ch-last (m, sp, c)
__device__ __half        g_y1l[256 * 225 * 128];
__device__ __half        g_w2f[128 * 6272];      // w2 single fp16: [n][(kh*7+kw)*128+ci]
__device__ float         g_x2f[20736 * 128];     // x_ fp32 ch-last [m][c] (for k5)
__device__ __nv_bfloat16 g_a3h[20736 * 144];     // k3 A operand split: [m][144]
__device__ __nv_bfloat16 g_a3l[20736 * 144];
__device__ __nv_bfloat16 g_w3h[128 * 144];
__device__ __nv_bfloat16 g_w3l[128 * 144];
__device__ __nv_bfloat16 g_y3h[20736 * 128];
__device__ __nv_bfloat16 g_y3l[20736 * 128];
__device__ __nv_bfloat16 g_w4h[128 * 128];
__device__ __nv_bfloat16 g_w4l[128 * 128];
__device__ float         g_merge[20736 * 128];   // fp32 ch-last [m][c]
__device__ float         g_logits[20736];

// ---------------- PTX helpers (baseline sm_80+) ----------------
__device__ __forceinline__ uint32_t smem_u32(const void* p) {
    uint32_t a;
    asm("{ .reg .u64 t; cvta.to.shared.u64 t, %1; cvt.u32.u64 %0, t; }" : "=r"(a) : "l"(p));
    return a;
}
__device__ __forceinline__ void cpa16(uint32_t dst, const void* src) {
    asm volatile("cp.async.ca.shared.global [%0], [%1], 16;" :: "r"(dst), "l"(src));
}
#define CP_COMMIT() asm volatile("cp.async.commit_group;" ::: "memory")
#define CP_WAIT2()  asm volatile("cp.async.wait_group 2;" ::: "memory")
#define CP_WAIT1()  asm volatile("cp.async.wait_group 1;" ::: "memory")
#define CP_WAIT0()  asm volatile("cp.async.wait_group 0;" ::: "memory")

__device__ __forceinline__ void ldsm4(uint32_t* r, uint32_t addr) {
    asm volatile("ldmatrix.sync.aligned.m8n8.x4.shared.b16 {%0,%1,%2,%3}, [%4];"
                 : "=r"(r[0]), "=r"(r[1]), "=r"(r[2]), "=r"(r[3]) : "r"(addr));
}
// bf16 MMA
__device__ __forceinline__ void mma16816(float* d, const uint32_t* a, const uint32_t* b) {
    asm volatile(
        "mma.sync.aligned.m16n8k16.row.col.f32.bf16.bf16.f32 "
        "{%0,%1,%2,%3}, {%4,%5,%6,%7}, {%8,%9}, {%0,%1,%2,%3};"
        : "+f"(d[0]), "+f"(d[1]), "+f"(d[2]), "+f"(d[3])
        : "r"(a[0]), "r"(a[1]), "r"(a[2]), "r"(a[3]), "r"(b[0]), "r"(b[1]));
}
// fp16 MMA
__device__ __forceinline__ void mma16816h(float* d, const uint32_t* a, const uint32_t* b) {
    asm volatile(
        "mma.sync.aligned.m16n8k16.row.col.f32.f16.f16.f32 "
        "{%0,%1,%2,%3}, {%4,%5,%6,%7}, {%8,%9}, {%0,%1,%2,%3};"
        : "+f"(d[0]), "+f"(d[1]), "+f"(d[2]), "+f"(d[3])
        : "r"(a[0]), "r"(a[1]), "r"(a[2]), "r"(a[3]), "r"(b[0]), "r"(b[1]));
}
__device__ __forceinline__ uint32_t cvt2(float f0, float f1) {          // bf16x2, lo=f0
    uint32_t r;
    asm("cvt.rn.bf16x2.f32 %0, %1, %2;" : "=r"(r) : "f"(f1), "f"(f0));
    return r;
}
__device__ __forceinline__ void split2(float v0, float v1, uint32_t& h, uint32_t& lo) {
    h = cvt2(v0, v1);
    float r0 = v0 - __uint_as_float(h << 16);
    float r1 = v1 - __uint_as_float(h & 0xFFFF0000u);
    lo = cvt2(r0, r1);
}
__device__ __forceinline__ uint32_t cvt2h(float f0, float f1) {         // f16x2, lo=f0
    uint32_t r;
    asm("cvt.rn.f16x2.f32 %0, %1, %2;" : "=r"(r) : "f"(f1), "f"(f0));
    return r;
}
__device__ __forceinline__ void split2h(float v0, float v1, uint32_t& h, uint32_t& lo) {
    h = cvt2h(v0, v1);
    float h0 = __half2float(__ushort_as_half((unsigned short)(h & 0xFFFFu)));
    float h1 = __half2float(__ushort_as_half((unsigned short)(h >> 16)));
    lo = cvt2h(v0 - h0, v1 - h1);
}

// ============================================================================
// prepA: merged kX (x transpose+split) + kB (per-ij B1 matrices)
// ============================================================================
__global__ __launch_bounds__(256) void prepA(const float* __restrict__ x,
                                             const float* __restrict__ w1)
{
    const int b = blockIdx.x;
    if (b < 2048) {
        __shared__ float s[225][33];
        const int tid = threadIdx.x;
        const int tx = tid & 31, ty = tid >> 5;
        const int ij0 = (b & 7) * 32;
        const int m   = b >> 3;
        const int nij = (ij0 + 32 <= 225) ? 32 : (225 - ij0);

        const float* xp = x + (long)m * 50625;
        for (int cc = 0; cc < 29; cc++) {
            int c = cc * 8 + ty;
            if (c < 225) {
                float v = (tx < nij) ? xp[c * 225 + ij0 + tx] : 0.f;
                s[c][tx] = v;
            }
        }
        __syncthreads();
        for (int ii = 0; ii < nij; ii++) {
            float v = (tid < 225) ? s[tid][ii] : 0.f;
            __nv_bfloat16 h = __float2bfloat16(v);
            long idx = ((long)(ij0 + ii) * 256 + m) * 256 + tid;
            g_xth[idx] = h;
            g_xtl[idx] = __float2bfloat16(v - __bfloat162float(h));
        }
    } else {
        const int bid = b - 2048;
        const int ij = bid >> 7, n = bid & 127;
        const int ip = ij / 15, jp = ij - ip * 15;
        const int k = threadIdx.x;
        float v = 0.f;
        if (k < 225) {
            int a = k / 15, bb = k - a * 15;
            v = w1[n * 841 + (a + 14 - ip) * 29 + (bb + 14 - jp)];
        }
        __nv_bfloat16 h = __float2bfloat16(v);
        long idx = ((long)ij * 128 + n) * 256 + k;
        g_B1h[idx] = h;
        g_B1l[idx] = __float2bfloat16(v - __bfloat162float(h));
    }
}

// ============================================================================
// prepB: merged kT2 (fp16 single) + kT3 + kT4 + kF.  grid 4568, block 256
// ============================================================================
__global__ __launch_bounds__(256) void prepB(const float* __restrict__ w2,
                                             const float* __restrict__ w3,
                                             const float* __restrict__ w4,
                                             const float* __restrict__ wgt)
{
    const int b = blockIdx.x;
    if (b < 3136) {
        int t = b * 256 + threadIdx.x;
        if (t < 128 * 6272) {
            int n = t / 6272, k = t - n * 6272;
            int g = k >> 7, ci = k & 127;
            g_w2f[t] = __float2half(w2[n * 6272 + ci * 49 + g]);
        }
    } else if (b < 3136 + 72) {
        int t = (b - 3136) * 256 + threadIdx.x;
        if (t < 128 * 144) {
            int n = t / 144, j = t - n * 144;
            float v = 0.f;
            if (j < 5)                  v = w3[n * 133 + j];
            else if (j >= 8 && j < 136) v = w3[n * 133 + j - 3];
            __nv_bfloat16 h = __float2bfloat16(v);
            g_w3h[t] = h;
            g_w3l[t] = __float2bfloat16(v - __bfloat162float(h));
        }
    } else if (b < 3136 + 72 + 64) {
        int t = (b - 3136 - 72) * 256 + threadIdx.x;
        if (t < 128 * 128) {
            float v = w4[t];
            __nv_bfloat16 h = __float2bfloat16(v);
            g_w4h[t] = h;
            g_w4l[t] = __float2bfloat16(v - __bfloat162float(h));
        }
    } else {
        int t = (b - 3136 - 72 - 64) * 256 + threadIdx.x;
        if (t < 20736 * 16) {
            int m = t >> 4, jj = t & 15;
            int j = (jj < 8) ? jj : (128 + jj);
            float v = (j < 5) ? wgt[j * 81 + (m % 81)] : 0.f;
            __nv_bfloat16 h = __float2bfloat16(v);
            long idx = (long)m * 144 + j;
            g_a3h[idx] = h;
            g_a3l[idx] = __float2bfloat16(v - __bfloat162float(h));
        }
    }
}

// ============================================================================
// k1: align-conv1 as MMA (bf16 3-term).  per ij: M=256, N=128, K=256(padded).
// grid (225, 2), block 256.  4 stages KT=64, double-buffered, 147KB.
// Epilogue emits y1 as fp16 2-plane split for k2.
// ============================================================================
#define LDA1    144
#define T1PLANE (128 * 144)
#define STAGE1  (4 * T1PLANE)
#define K1_SMEM (2 * STAGE1)       // 147456

__global__ __launch_bounds__(256) void k1_mma(
    const float* __restrict__ b1, const float* __restrict__ bn1)
{
    extern __shared__ char smem[];
    const uint32_t sb = smem_u32(smem);
    const int tid = threadIdx.x;
    const int w = tid >> 5, l = tid & 31;
    const int ij = blockIdx.x;
    const int m0 = blockIdx.y * 128;
    const int warp_m = (w >> 2) * 64;
    const int warp_n = (w & 3) * 32;

    const int row = tid & 127, ver = tid >> 7;
    const __nv_bfloat16* asrc = (ver ? g_xtl : g_xth) + ((long)ij * 256 + m0 + row) * 256;
    const __nv_bfloat16* bsrc = (ver ? g_B1l : g_B1h) + ((long)ij * 128 + row) * 256;
    const uint32_t dA = sb + ver * T1PLANE + row * LDA1;
    const uint32_t dB = sb + 2 * T1PLANE + ver * T1PLANE + row * LDA1;

    float acc[4][4][4];
#pragma unroll
    for (int i = 0; i < 4; i++)
#pragma unroll
        for (int j = 0; j < 4; j++)
#pragma unroll
            for (int c = 0; c < 4; c++) acc[i][j][c] = 0.f;

    auto load_stage = [&](int s, uint32_t off) {
#pragma unroll
        for (int j = 0; j < 8; j++) {
            cpa16(dA + off + j * 16, asrc + s * 64 + j * 8);
            cpa16(dB + off + j * 16, bsrc + s * 64 + j * 8);
        }
    };

    const uint32_t aAddrM = (warp_m + (l & 15)) * LDA1 + ((l >> 4) << 4);
    const uint32_t bAddrN = (warp_n + (l & 7) + ((l >> 4) << 3)) * LDA1 + (((l >> 3) & 1) << 4);
    auto compute_stage = [&](uint32_t off) {
        uint32_t base = sb + off;
#pragma unroll
        for (int ks = 0; ks < 4; ks++) {
            uint32_t ko = ks * 32;
            uint32_t ah[4][4], al[4][4];
#pragma unroll
            for (int mi = 0; mi < 4; mi++) {
                uint32_t ad = base + aAddrM + mi * (16 * LDA1) + ko;
                ldsm4(ah[mi], ad);
                ldsm4(al[mi], ad + T1PLANE);
            }
            uint32_t bh[2][4], bl[2][4];
#pragma unroll
            for (int nb = 0; nb < 2; nb++) {
                uint32_t bd = base + 2 * T1PLANE + bAddrN + nb * (16 * LDA1) + ko;
                ldsm4(bh[nb], bd);
                ldsm4(bl[nb], bd + T1PLANE);
            }
#pragma unroll
            for (int mi = 0; mi < 4; mi++)
#pragma unroll
                for (int nj = 0; nj < 4; nj++)
                    mma16816(acc[mi][nj], ah[mi], &bh[nj >> 1][(nj & 1) * 2]);
#pragma unroll
            for (int mi = 0; mi < 4; mi++)
#pragma unroll
                for (int nj = 0; nj < 4; nj++)
                    mma16816(acc[mi][nj], ah[mi], &bl[nj >> 1][(nj & 1) * 2]);
#pragma unroll
            for (int mi = 0; mi < 4; mi++)
#pragma unroll
                for (int nj = 0; nj < 4; nj++)
                    mma16816(acc[mi][nj], al[mi], &bh[nj >> 1][(nj & 1) * 2]);
        }
    };

    load_stage(0, 0);
    CP_COMMIT();
    for (int s = 0; s < 4; s++) {
        if (s + 1 < 4) load_stage(s + 1, ((s + 1) & 1) * STAGE1);
        CP_COMMIT();
        CP_WAIT1();
        __syncthreads();
        compute_stage((s & 1) * STAGE1);
        __syncthreads();
    }

    float sc[4][2], sh[4][2];
#pragma unroll
    for (int nj = 0; nj < 4; nj++)
#pragma unroll
        for (int q = 0; q < 2; q++) {
            int n = warp_n + nj * 8 + (l & 3) * 2 + q;
            float g = bn1[n], be = bn1[128 + n], mu = bn1[256 + n], va = bn1[384 + n];
            float s = g * rsqrtf(va + EPSV);
            sc[nj][q] = s;
            sh[nj][q] = (b1[n] - mu) * s + be;
        }
#pragma unroll
    for (int mi = 0; mi < 4; mi++)
#pragma unroll
        for (int half = 0; half < 2; half++) {
            int m = m0 + warp_m + mi * 16 + (l >> 2) + half * 8;
            long base = ((long)m * 225 + ij) * 128;
#pragma unroll
            for (int nj = 0; nj < 4; nj++) {
                int n0 = warp_n + nj * 8 + (l & 3) * 2;
                float v0 = fmaxf(fmaf(acc[mi][nj][half * 2 + 0], sc[nj][0], sh[nj][0]), 0.f);
                float v1 = fmaxf(fmaf(acc[mi][nj][half * 2 + 1], sc[nj][1], sh[nj][1]), 0.f);
                uint32_t h, lo;
                split2h(v0, v1, h, lo);
                *(uint32_t*)&g_y1h[base + n0] = h;
                *(uint32_t*)&g_y1l[base + n0] = lo;
            }
        }
}

// ============================================================================
// k2: 7x7 conv MMA fp16 2-term: D = (Ah+Al)*B.  M-tile 144 -> grid 144 (one
// wave), block 288 (9 warps, warp tile 16x128), 4-stage cp.async ring (130KB).
// ============================================================================
#define LDA    80
#define A2_V   (144 * 80)              // 11520
#define B2_V   (128 * 80)              // 10240
#define STG2   (2 * A2_V + B2_V)       // 33280 (Ah, Al, B)
#define K2_SMEM (4 * STG2)             // 133120

__global__ __launch_bounds__(288, 1) void k2_mma(
    const float* __restrict__ b2, const float* __restrict__ bn2)
{
    extern __shared__ char smem[];
    const uint32_t sb = smem_u32(smem);
    const int tid = threadIdx.x;
    const int w = tid >> 5, l = tid & 31;   // 9 warps
    const int m0 = blockIdx.x * 144;

    // ---- A loader: 144 rows x 2 chunks = 288 threads ----
    const int ar = tid >> 1;
    const int ac = (tid & 1) * 32;
    const int ae = ac >> 1;
    const int gm = m0 + ar;
    const int bv = gm / 81;
    const int pos = gm - bv * 81;
    const int oh = pos / 9, ow = pos - oh * 9;
    const long a_base = ((long)bv * 225 + oh * 15 + ow) * 128;
    const uint32_t dstA = sb + ar * LDA + ac;
    // ---- B loader: threads 0..255, 128 rows x 2 chunks ----
    const int br = (tid < 256) ? (tid >> 1) : 0;
    const __half* wf_src = g_w2f + (long)br * 6272;
    const uint32_t dstB = sb + 2 * A2_V + br * LDA + ac;

    float acc[16][4];
#pragma unroll
    for (int i = 0; i < 16; i++)
#pragma unroll
        for (int c = 0; c < 4; c++) acc[i][c] = 0.f;

    auto load_stage = [&](int s, uint32_t off) {
        int g  = s >> 2;
        int kh = g / 7, kw = g - kh * 7;
        long aoff = a_base + (kh * 15 + kw) * 128 + (s & 3) * 32 + ae;
        const __half* pah = g_y1h + aoff;
        const __half* pal = g_y1l + aoff;
        uint32_t dA = dstA + off;
        cpa16(dA, pah);
        cpa16(dA + 16, pah + 8);
        cpa16(dA + A2_V, pal);
        cpa16(dA + A2_V + 16, pal + 8);
        if (tid < 256) {
            long boff = (long)s * 32 + ae;
            uint32_t dB = dstB + off;
            cpa16(dB, wf_src + boff);
            cpa16(dB + 16, wf_src + boff + 8);
        }
    };

    const uint32_t aAddrM = (w * 16 + (l & 15)) * LDA + ((l >> 4) << 4);
    const uint32_t bAddrN = ((l & 7) + ((l >> 4) << 3)) * LDA + (((l >> 3) & 1) << 4);
    auto compute_stage = [&](uint32_t off) {
        uint32_t base = sb + off;
#pragma unroll
        for (int ks = 0; ks < 2; ks++) {
            uint32_t ko = ks * 32;
            uint32_t ah[4], al[4];
            {
                uint32_t ad = base + aAddrM + ko;
                ldsm4(ah, ad);
                ldsm4(al, ad + A2_V);
            }
            uint32_t bh[8][4];
#pragma unroll
            for (int nb = 0; nb < 8; nb++) {
                uint32_t bd = base + 2 * A2_V + bAddrN + nb * (16 * LDA) + ko;
                ldsm4(bh[nb], bd);
            }
#pragma unroll
            for (int nj = 0; nj < 16; nj++)
                mma16816h(acc[nj], ah, &bh[nj >> 1][(nj & 1) * 2]);
#pragma unroll
            for (int nj = 0; nj < 16; nj++)
                mma16816h(acc[nj], al, &bh[nj >> 1][(nj & 1) * 2]);
        }
    };

    // ---- 4-deep pipeline ----
    load_stage(0, 0);            CP_COMMIT();
    load_stage(1, STG2);         CP_COMMIT();
    load_stage(2, 2 * STG2);     CP_COMMIT();
    for (int s = 0; s < 196; s++) {
        CP_WAIT2();
        __syncthreads();
        compute_stage((s & 3) * STG2);
        if (s + 3 < 196) load_stage(s + 3, ((s + 3) & 3) * STG2);
        CP_COMMIT();
    }

    // ---- epilogue ----
    float sc[16][2], sh[16][2];
#pragma unroll
    for (int nj = 0; nj < 16; nj++)
#pragma unroll
        for (int q = 0; q < 2; q++) {
            int n = nj * 8 + (l & 3) * 2 + q;
            float g = bn2[n], be = bn2[128 + n], mu = bn2[256 + n], va = bn2[384 + n];
            float s = g * rsqrtf(va + EPSV);
            sc[nj][q] = s;
            sh[nj][q] = (b2[n] - mu) * s + be;
        }
#pragma unroll
    for (int half = 0; half < 2; half++) {
        int m = m0 + w * 16 + (l >> 2) + half * 8;
#pragma unroll
        for (int nj = 0; nj < 16; nj++) {
            int n0 = nj * 8 + (l & 3) * 2;
            float v0 = fmaxf(fmaf(acc[nj][half * 2 + 0], sc[nj][0], sh[nj][0]), 0.f);
            float v1 = fmaxf(fmaf(acc[nj][half * 2 + 1], sc[nj][1], sh[nj][1]), 0.f);
            *(float2*)&g_x2f[(long)m * 128 + n0] = make_float2(v0, v1);
            uint32_t h, lo;
            split2(v0, v1, h, lo);
            *(uint32_t*)&g_a3h[(long)m * 144 + 8 + n0] = h;
            *(uint32_t*)&g_a3l[(long)m * 144 + 8 + n0] = lo;
        }
    }
}

// ============================================================================
// k3: conv1x1 144->128 MMA (monolithic smem), grid 162, block 256
// ============================================================================
#define LDA3    304
#define T3PLANE (128 * 304)
#define K3_SMEM (4 * T3PLANE)

__global__ __launch_bounds__(256) void k3_mma(
    const float* __restrict__ b3, const float* __restrict__ bn3)
{
    extern __shared__ char smem[];
    const uint32_t sb = smem_u32(smem);
    const int tid = threadIdx.x;
    const int w = tid >> 5, l = tid & 31;
    const int m0 = blockIdx.x * 128;
    const int warp_m = (w >> 2) * 64;
    const int warp_n = (w & 3) * 32;

    const int row = tid & 127, ver = tid >> 7;
    const __nv_bfloat16* asrc = (ver ? g_a3l : g_a3h) + (long)(m0 + row) * 144;
    const __nv_bfloat16* bsrc = (ver ? g_w3l : g_w3h) + row * 144;
    const uint32_t dA = sb + ver * T3PLANE + row * LDA3;
    const uint32_t dB = sb + 2 * T3PLANE + ver * T3PLANE + row * LDA3;
#pragma unroll
    for (int j = 0; j < 18; j++) {
        cpa16(dA + j * 16, asrc + j * 8);
        cpa16(dB + j * 16, bsrc + j * 8);
    }
    CP_COMMIT();

    float acc[4][4][4];
#pragma unroll
    for (int i = 0; i < 4; i++)
#pragma unroll
        for (int j = 0; j < 4; j++)
#pragma unroll
            for (int c = 0; c < 4; c++) acc[i][j][c] = 0.f;

    CP_WAIT0();
    __syncthreads();

    const uint32_t aAddrM = (warp_m + (l & 15)) * LDA3 + ((l >> 4) << 4);
    const uint32_t bAddrN = (warp_n + (l & 7) + ((l >> 4) << 3)) * LDA3 + (((l >> 3) & 1) << 4);
#pragma unroll
    for (int ks = 0; ks < 9; ks++) {
        uint32_t ko = ks * 32;
        uint32_t ah[4][4], al[4][4];
#pragma unroll
        for (int mi = 0; mi < 4; mi++) {
            uint32_t ad = sb + aAddrM + mi * (16 * LDA3) + ko;
            ldsm4(ah[mi], ad);
            ldsm4(al[mi], ad + T3PLANE);
        }
        uint32_t bh[2][4], bl[2][4];
#pragma unroll
        for (int nb = 0; nb < 2; nb++) {
            uint32_t bd = sb + 2 * T3PLANE + bAddrN + nb * (16 * LDA3) + ko;
            ldsm4(bh[nb], bd);
            ldsm4(bl[nb], bd + T3PLANE);
        }
#pragma unroll
        for (int mi = 0; mi < 4; mi++)
#pragma unroll
            for (int nj = 0; nj < 4; nj++)
                mma16816(acc[mi][nj], ah[mi], &bh[nj >> 1][(nj & 1) * 2]);
#pragma unroll
        for (int mi = 0; mi < 4; mi++)
#pragma unroll
            for (int nj = 0; nj < 4; nj++)
                mma16816(acc[mi][nj], ah[mi], &bl[nj >> 1][(nj & 1) * 2]);
#pragma unroll
        for (int mi = 0; mi < 4; mi++)
#pragma unroll
            for (int nj = 0; nj < 4; nj++)
                mma16816(acc[mi][nj], al[mi], &bh[nj >> 1][(nj & 1) * 2]);
    }

    float sc[4][2], sh[4][2];
#pragma unroll
    for (int nj = 0; nj < 4; nj++)
#pragma unroll
        for (int q = 0; q < 2; q++) {
            int n = warp_n + nj * 8 + (l & 3) * 2 + q;
            float g = bn3[n], be = bn3[128 + n], mu = bn3[256 + n], va = bn3[384 + n];
            float s = g * rsqrtf(va + EPSV);
            sc[nj][q] = s;
            sh[nj][q] = (b3[n] - mu) * s + be;
        }
#pragma unroll
    for (int mi = 0; mi < 4; mi++)
#pragma unroll
        for (int half = 0; half < 2; half++) {
            int m = m0 + warp_m + mi * 16 + (l >> 2) + half * 8;
#pragma unroll
            for (int nj = 0; nj < 4; nj++) {
                int n0 = warp_n + nj * 8 + (l & 3) * 2;
                float v0 = fmaxf(fmaf(acc[mi][nj][half * 2 + 0], sc[nj][0], sh[nj][0]), 0.f);
                float v1 = fmaxf(fmaf(acc[mi][nj][half * 2 + 1], sc[nj][1], sh[nj][1]), 0.f);
                uint32_t h, lo;
                split2(v0, v1, h, lo);
                *(uint32_t*)&g_y3h[(long)m * 128 + n0] = h;
                *(uint32_t*)&g_y3l[(long)m * 128 + n0] = lo;
            }
        }
}

// ============================================================================
// k4: conv1x1 128->128 MMA (monolithic smem) -> g_merge fp32 ch-last
// ============================================================================
#define LDA4    272
#define T4PLANE (128 * 272)
#define K4_SMEM (4 * T4PLANE)

__global__ __launch_bounds__(256) void k4_mma(
    const float* __restrict__ b4, const float* __restrict__ bn4)
{
    extern __shared__ char smem[];
    const uint32_t sb = smem_u32(smem);
    const int tid = threadIdx.x;
    const int w = tid >> 5, l = tid & 31;
    const int m0 = blockIdx.x * 128;
    const int warp_m = (w >> 2) * 64;
    const int warp_n = (w & 3) * 32;

    const int row = tid & 127, ver = tid >> 7;
    const __nv_bfloat16* asrc = (ver ? g_y3l : g_y3h) + (long)(m0 + row) * 128;
    const __nv_bfloat16* bsrc = (ver ? g_w4l : g_w4h) + row * 128;
    const uint32_t dA = sb + ver * T4PLANE + row * LDA4;
    const uint32_t dB = sb + 2 * T4PLANE + ver * T4PLANE + row * LDA4;
#pragma unroll
    for (int j = 0; j < 16; j++) {
        cpa16(dA + j * 16, asrc + j * 8);
        cpa16(dB + j * 16, bsrc + j * 8);
    }
    CP_COMMIT();

    float acc[4][4][4];
#pragma unroll
    for (int i = 0; i < 4; i++)
#pragma unroll
        for (int j = 0; j < 4; j++)
#pragma unroll
            for (int c = 0; c < 4; c++) acc[i][j][c] = 0.f;

    CP_WAIT0();
    __syncthreads();

    const uint32_t aAddrM = (warp_m + (l & 15)) * LDA4 + ((l >> 4) << 4);
    const uint32_t bAddrN = (warp_n + (l & 7) + ((l >> 4) << 3)) * LDA4 + (((l >> 3) & 1) << 4);
#pragma unroll
    for (int ks = 0; ks < 8; ks++) {
        uint32_t ko = ks * 32;
        uint32_t ah[4][4], al[4][4];
#pragma unroll
        for (int mi = 0; mi < 4; mi++) {
            uint32_t ad = sb + aAddrM + mi * (16 * LDA4) + ko;
            ldsm4(ah[mi], ad);
            ldsm4(al[mi], ad + T4PLANE);
        }
        uint32_t bh[2][4], bl[2][4];
#pragma unroll
        for (int nb = 0; nb < 2; nb++) {
            uint32_t bd = sb + 2 * T4PLANE + bAddrN + nb * (16 * LDA4) + ko;
            ldsm4(bh[nb], bd);
            ldsm4(bl[nb], bd + T4PLANE);
        }
#pragma unroll
        for (int mi = 0; mi < 4; mi++)
#pragma unroll
            for (int nj = 0; nj < 4; nj++)
                mma16816(acc[mi][nj], ah[mi], &bh[nj >> 1][(nj & 1) * 2]);
#pragma unroll
        for (int mi = 0; mi < 4; mi++)
#pragma unroll
            for (int nj = 0; nj < 4; nj++)
                mma16816(acc[mi][nj], ah[mi], &bl[nj >> 1][(nj & 1) * 2]);
#pragma unroll
        for (int mi = 0; mi < 4; mi++)
#pragma unroll
            for (int nj = 0; nj < 4; nj++)
                mma16816(acc[mi][nj], al[mi], &bh[nj >> 1][(nj & 1) * 2]);
    }

    float sc[4][2], sh[4][2];
#pragma unroll
    for (int nj = 0; nj < 4; nj++)
#pragma unroll
        for (int q = 0; q < 2; q++) {
            int n = warp_n + nj * 8 + (l & 3) * 2 + q;
            float g = bn4[n], be = bn4[128 + n], mu = bn4[256 + n], va = bn4[384 + n];
            float s = g * rsqrtf(va + EPSV);
            sc[nj][q] = s;
            sh[nj][q] = (b4[n] - mu) * s + be;
        }
#pragma unroll
    for (int mi = 0; mi < 4; mi++)
#pragma unroll
        for (int half = 0; half < 2; half++) {
            int m = m0 + warp_m + mi * 16 + (l >> 2) + half * 8;
#pragma unroll
            for (int nj = 0; nj < 4; nj++) {
                int n0 = warp_n + nj * 8 + (l & 3) * 2;
                float v0 = fmaxf(fmaf(acc[mi][nj][half * 2 + 0], sc[nj][0], sh[nj][0]), 0.f);
                float v1 = fmaxf(fmaf(acc[mi][nj][half * 2 + 1], sc[nj][1], sh[nj][1]), 0.f);
                *(float2*)&g_merge[(long)m * 128 + n0] = make_float2(v0, v1);
            }
        }
}

// ============================================================================
// k5: attention logits, wa1 cached in smem.  grid 1296, block 256
// ============================================================================
__global__ __launch_bounds__(256) void k5_logits(
    const float* __restrict__ wa1, const float* __restrict__ ba1,
    const float* __restrict__ bna, const float* __restrict__ wa2,
    const float* __restrict__ ba2)
{
    __shared__ float wa1s[64][129];
    __shared__ float xs[4][128];
    __shared__ float wa2s[64];
    __shared__ float bnsc[64], bnsh[64];
    __shared__ float red[8];
    const int tid = threadIdx.x;
    const int m0 = blockIdx.x * 16;
    const int o  = tid & 63;
    const int mi = tid >> 6;

    for (int i = tid; i < 64 * 128; i += 256)
        wa1s[i >> 7][i & 127] = wa1[i];
    if (tid < 64) {
        float g = bna[tid], be = bna[64 + tid], mu = bna[128 + tid], va = bna[192 + tid];
        float s = g * rsqrtf(va + EPSV);
        bnsc[tid] = s;
        bnsh[tid] = (ba1[tid] - mu) * s + be;
        wa2s[tid] = wa2[tid];
    }
    const float ba2v = ba2[0];
    __syncthreads();

    for (int it = 0; it < 4; it++) {
        {
            int i = tid;
            xs[i >> 7][i & 127] = g_x2f[(long)(m0 + it * 4 + (i >> 7)) * 128 + (i & 127)];
            i += 256;
            xs[i >> 7][i & 127] = g_x2f[(long)(m0 + it * 4 + (i >> 7)) * 128 + (i & 127)];
        }
        __syncthreads();
        float acc = 0.f;
#pragma unroll 8
        for (int c = 0; c < 128; c++) acc = fmaf(wa1s[o][c], xs[mi][c], acc);
        float t = fmaxf(fmaf(acc, bnsc[o], bnsh[o]), 0.f);
        float p = wa2s[o] * t;
#pragma unroll
        for (int off = 16; off > 0; off >>= 1) p += __shfl_down_sync(0xffffffffu, p, off);
        if ((tid & 31) == 0) red[tid >> 5] = p;
        __syncthreads();
        if (o == 0) g_logits[m0 + it * 4 + mi] = red[mi * 2] + red[mi * 2 + 1] + ba2v;
        __syncthreads();
    }
}

// ============================================================================
// k6: softmax(81) + attention-pool + final linear (128->6).  grid 256, block 128
// ============================================================================
__global__ __launch_bounds__(128) void k6_final(
    const float* __restrict__ wl, const float* __restrict__ bl,
    float* __restrict__ out)
{
    __shared__ float att[81];
    __shared__ float pooled[128];
    __shared__ float red[4];
    const int b = blockIdx.x;
    const int t = threadIdx.x;

    float v = (t < 81) ? g_logits[b * 81 + t] : -1e30f;
    float mx = v;
#pragma unroll
    for (int off = 16; off > 0; off >>= 1) mx = fmaxf(mx, __shfl_xor_sync(0xffffffffu, mx, off));
    if ((t & 31) == 0) red[t >> 5] = mx;
    __syncthreads();
    mx = fmaxf(fmaxf(red[0], red[1]), fmaxf(red[2], red[3]));
    float e = (t < 81) ? expf(v - mx) : 0.f;
    __syncthreads();
    float sm = e;
#pragma unroll
    for (int off = 16; off > 0; off >>= 1) sm += __shfl_xor_sync(0xffffffffu, sm, off);
    if ((t & 31) == 0) red[t >> 5] = sm;
    __syncthreads();
    sm = red[0] + red[1] + red[2] + red[3];
    if (t < 81) att[t] = e / sm;
    __syncthreads();

    float acc = 0.f;
    const float* mr = g_merge + (long)b * 81 * 128 + t;
#pragma unroll 9
    for (int p = 0; p < 81; p++) acc = fmaf(att[p], mr[p * 128], acc);
    pooled[t] = acc;
    __syncthreads();

    if (t < 6) {
        float s2 = bl[t];
        const float* wr = wl + t * 128;
#pragma unroll 8
        for (int o = 0; o < 128; o++) s2 = fmaf(wr[o], pooled[o], s2);
        out[b * 6 + t] = s2;
    }
}

// ============================================================================
extern "C" void kernel_launch(void* const* d_in, const int* in_sizes, int n_in,
                              void* d_out, int out_size)
{
    const float* x    = (const float*)d_in[0];
    const float* w1   = (const float*)d_in[1];
    const float* b1   = (const float*)d_in[2];
    const float* bn1  = (const float*)d_in[3];
    const float* w2   = (const float*)d_in[4];
    const float* b2   = (const float*)d_in[5];
    const float* bn2  = (const float*)d_in[6];
    const float* wgt  = (const float*)d_in[7];
    const float* w3   = (const float*)d_in[8];
    const float* b3   = (const float*)d_in[9];
    const float* bn3  = (const float*)d_in[10];
    const float* w4   = (const float*)d_in[11];
    const float* b4   = (const float*)d_in[12];
    const float* bn4  = (const float*)d_in[13];
    const float* wa1  = (const float*)d_in[14];
    const float* ba1  = (const float*)d_in[15];
    const float* bna  = (const float*)d_in[16];
    const float* wa2  = (const float*)d_in[17];
    const float* ba2  = (const float*)d_in[18];
    const float* wl   = (const float*)d_in[19];
    const float* bl   = (const float*)d_in[20];
    float* out = (float*)d_out;

    cudaFuncSetAttribute(k1_mma, cudaFuncAttributeMaxDynamicSharedMemorySize, K1_SMEM);
    cudaFuncSetAttribute(k2_mma, cudaFuncAttributeMaxDynamicSharedMemorySize, K2_SMEM);
    cudaFuncSetAttribute(k3_mma, cudaFuncAttributeMaxDynamicSharedMemorySize, K3_SMEM);
    cudaFuncSetAttribute(k4_mma, cudaFuncAttributeMaxDynamicSharedMemorySize, K4_SMEM);

    // launch order keeps k2_mma in ncu's sampled slot (4th launch)
    prepA<<<30848, 256>>>(x, w1);                  // 1
    dim3 g1(225, 2);
    k1_mma<<<g1, 256, K1_SMEM>>>(b1, bn1);         // 2
    prepB<<<4568, 256>>>(w2, w3, w4, wgt);         // 3
    k2_mma<<<144, 288, K2_SMEM>>>(b2, bn2);        // 4  <-- profiled, one wave
    k3_mma<<<162, 256, K3_SMEM>>>(b3, bn3);        // 5
    k4_mma<<<162, 256, K4_SMEM>>>(b4, bn4);        // 6
    k5_logits<<<1296, 256>>>(wa1, ba1, bna, wa2, ba2); // 7
    k6_final<<<256, 128>>>(wl, bl, out);           // 8
}

// round 16
// speedup vs baseline: 1.5265x; 1.0178x over previous
#include <cuda_runtime.h>
#include <cuda_bf16.h>
#include <cuda_fp16.h>
#include <cstdint>

#define EPSV 1e-5f

typedef unsigned long long ull;

// ---------------- scratch buffers (static, allocation-free) ----------------
__device__ __half g_xth[225 * 256 * 256];  // x transposed+split fp16: [ij][m][ck<=255]
__device__ __half g_xtl[225 * 256 * 256];
__device__ __half g_B1f[225 * 128 * 256];  // per-ij conv1 B, single fp16
__device__ __half g_y1h[256 * 225 * 128];  // y1 fp16 split, ch-last (m, sp, c)
__device__ __half g_y1l[256 * 225 * 128];
__device__ __half g_w2f[128 * 6272];       // w2 single fp16: [n][(kh*7+kw)*128+ci]
__device__ float  g_x2f[20736 * 128];      // x_ fp32 ch-last [m][c] (for k5)
__device__ __half g_a3h[20736 * 144];      // k3 A operand fp16 split: [m][144]
__device__ __half g_a3l[20736 * 144];
__device__ __half g_w3f[128 * 144];        // w3 single fp16 (padded cols)
__device__ __half g_y3h[20736 * 128];
__device__ __half g_y3l[20736 * 128];
__device__ __half g_w4f[128 * 128];        // w4 single fp16
__device__ float  g_merge[20736 * 128];    // fp32 ch-last [m][c]
__device__ float  g_logits[20736];

// ---------------- PTX helpers (baseline sm_80+) ----------------
__device__ __forceinline__ uint32_t smem_u32(const void* p) {
    uint32_t a;
    asm("{ .reg .u64 t; cvta.to.shared.u64 t, %1; cvt.u32.u64 %0, t; }" : "=r"(a) : "l"(p));
    return a;
}
__device__ __forceinline__ void cpa16(uint32_t dst, const void* src) {
    asm volatile("cp.async.ca.shared.global [%0], [%1], 16;" :: "r"(dst), "l"(src));
}
#define CP_COMMIT() asm volatile("cp.async.commit_group;" ::: "memory")
#define CP_WAIT2()  asm volatile("cp.async.wait_group 2;" ::: "memory")
#define CP_WAIT1()  asm volatile("cp.async.wait_group 1;" ::: "memory")
#define CP_WAIT0()  asm volatile("cp.async.wait_group 0;" ::: "memory")

__device__ __forceinline__ void ldsm4(uint32_t* r, uint32_t addr) {
    asm volatile("ldmatrix.sync.aligned.m8n8.x4.shared.b16 {%0,%1,%2,%3}, [%4];"
                 : "=r"(r[0]), "=r"(r[1]), "=r"(r[2]), "=r"(r[3]) : "r"(addr));
}
// fp16 MMA
__device__ __forceinline__ void mma16816h(float* d, const uint32_t* a, const uint32_t* b) {
    asm volatile(
        "mma.sync.aligned.m16n8k16.row.col.f32.f16.f16.f32 "
        "{%0,%1,%2,%3}, {%4,%5,%6,%7}, {%8,%9}, {%0,%1,%2,%3};"
        : "+f"(d[0]), "+f"(d[1]), "+f"(d[2]), "+f"(d[3])
        : "r"(a[0]), "r"(a[1]), "r"(a[2]), "r"(a[3]), "r"(b[0]), "r"(b[1]));
}
__device__ __forceinline__ uint32_t cvt2h(float f0, float f1) {         // f16x2, lo=f0
    uint32_t r;
    asm("cvt.rn.f16x2.f32 %0, %1, %2;" : "=r"(r) : "f"(f1), "f"(f0));
    return r;
}
__device__ __forceinline__ void split2h(float v0, float v1, uint32_t& h, uint32_t& lo) {
    h = cvt2h(v0, v1);
    float h0 = __half2float(__ushort_as_half((unsigned short)(h & 0xFFFFu)));
    float h1 = __half2float(__ushort_as_half((unsigned short)(h >> 16)));
    lo = cvt2h(v0 - h0, v1 - h1);
}

// ============================================================================
// prepA: merged kX (x transpose + fp16 split) + kB (per-ij B1, single fp16)
// grid 2048 + 28800 = 30848, block 256
// ============================================================================
__global__ __launch_bounds__(256) void prepA(const float* __restrict__ x,
                                             const float* __restrict__ w1)
{
    const int b = blockIdx.x;
    if (b < 2048) {
        __shared__ float s[225][33];
        const int tid = threadIdx.x;
        const int tx = tid & 31, ty = tid >> 5;
        const int ij0 = (b & 7) * 32;
        const int m   = b >> 3;
        const int nij = (ij0 + 32 <= 225) ? 32 : (225 - ij0);

        const float* xp = x + (long)m * 50625;
        for (int cc = 0; cc < 29; cc++) {
            int c = cc * 8 + ty;
            if (c < 225) {
                float v = (tx < nij) ? xp[c * 225 + ij0 + tx] : 0.f;
                s[c][tx] = v;
            }
        }
        __syncthreads();
        for (int ii = 0; ii < nij; ii++) {
            float v = (tid < 225) ? s[tid][ii] : 0.f;
            __half h = __float2half(v);
            long idx = ((long)(ij0 + ii) * 256 + m) * 256 + tid;
            g_xth[idx] = h;
            g_xtl[idx] = __float2half(v - __half2float(h));
        }
    } else {
        const int bid = b - 2048;
        const int ij = bid >> 7, n = bid & 127;
        const int ip = ij / 15, jp = ij - ip * 15;
        const int k = threadIdx.x;
        float v = 0.f;
        if (k < 225) {
            int a = k / 15, bb = k - a * 15;
            v = w1[n * 841 + (a + 14 - ip) * 29 + (bb + 14 - jp)];
        }
        g_B1f[((long)ij * 128 + n) * 256 + k] = __float2half(v);
    }
}

// ============================================================================
// prepB: merged w2/w3/w4 (single fp16) + kF (a3 cols, fp16 split)
// grid 4568, block 256
// ============================================================================
__global__ __launch_bounds__(256) void prepB(const float* __restrict__ w2,
                                             const float* __restrict__ w3,
                                             const float* __restrict__ w4,
                                             const float* __restrict__ wgt)
{
    const int b = blockIdx.x;
    if (b < 3136) {
        int t = b * 256 + threadIdx.x;
        if (t < 128 * 6272) {
            int n = t / 6272, k = t - n * 6272;
            int g = k >> 7, ci = k & 127;
            g_w2f[t] = __float2half(w2[n * 6272 + ci * 49 + g]);
        }
    } else if (b < 3136 + 72) {
        int t = (b - 3136) * 256 + threadIdx.x;
        if (t < 128 * 144) {
            int n = t / 144, j = t - n * 144;
            float v = 0.f;
            if (j < 5)                  v = w3[n * 133 + j];
            else if (j >= 8 && j < 136) v = w3[n * 133 + j - 3];
            g_w3f[t] = __float2half(v);
        }
    } else if (b < 3136 + 72 + 64) {
        int t = (b - 3136 - 72) * 256 + threadIdx.x;
        if (t < 128 * 128) g_w4f[t] = __float2half(w4[t]);
    } else {
        int t = (b - 3136 - 72 - 64) * 256 + threadIdx.x;
        if (t < 20736 * 16) {
            int m = t >> 4, jj = t & 15;
            int j = (jj < 8) ? jj : (128 + jj);
            float v = (j < 5) ? wgt[j * 81 + (m % 81)] : 0.f;
            __half h = __float2half(v);
            long idx = (long)m * 144 + j;
            g_a3h[idx] = h;
            g_a3l[idx] = __float2half(v - __half2float(h));
        }
    }
}

// ============================================================================
// k1: align-conv1 MMA, fp16 2-term: D = (Ah+Al)*B.  per ij: M=256, N=128,
// K=256(padded).  grid (225, 2), block 256.  4 stages KT=64, 3 planes, 110KB.
// ============================================================================
#define LDA1    144
#define T1PLANE (128 * 144)
#define STG1    (3 * T1PLANE)      // Ah, Al, B
#define K1_SMEM (2 * STG1)         // 110592

__global__ __launch_bounds__(256) void k1_mma(
    const float* __restrict__ b1, const float* __restrict__ bn1)
{
    extern __shared__ char smem[];
    const uint32_t sb = smem_u32(smem);
    const int tid = threadIdx.x;
    const int w = tid >> 5, l = tid & 31;
    const int ij = blockIdx.x;
    const int m0 = blockIdx.y * 128;
    const int warp_m = (w >> 2) * 64;
    const int warp_n = (w & 3) * 32;

    const int row = tid & 127, half_ = tid >> 7;
    // A: half_ selects plane (0=Ah, 1=Al); each thread loads its row's 128B chunk
    const __half* asrc = (half_ ? g_xtl : g_xth) + ((long)ij * 256 + m0 + row) * 256;
    const uint32_t dA = sb + half_ * T1PLANE + row * LDA1;
    // B: single plane; each thread loads half a row (64B)
    const __half* bsrc = g_B1f + ((long)ij * 128 + row) * 256;
    const uint32_t dB = sb + 2 * T1PLANE + row * LDA1 + half_ * 64;

    float acc[4][4][4];
#pragma unroll
    for (int i = 0; i < 4; i++)
#pragma unroll
        for (int j = 0; j < 4; j++)
#pragma unroll
            for (int c = 0; c < 4; c++) acc[i][j][c] = 0.f;

    auto load_stage = [&](int s, uint32_t off) {
#pragma unroll
        for (int j = 0; j < 8; j++)
            cpa16(dA + off + j * 16, asrc + s * 64 + j * 8);
#pragma unroll
        for (int j = 0; j < 4; j++)
            cpa16(dB + off + j * 16, bsrc + s * 64 + half_ * 32 + j * 8);
    };

    const uint32_t aAddrM = (warp_m + (l & 15)) * LDA1 + ((l >> 4) << 4);
    const uint32_t bAddrN = (warp_n + (l & 7) + ((l >> 4) << 3)) * LDA1 + (((l >> 3) & 1) << 4);
    auto compute_stage = [&](uint32_t off) {
        uint32_t base = sb + off;
#pragma unroll
        for (int ks = 0; ks < 4; ks++) {
            uint32_t ko = ks * 32;
            uint32_t ah[4][4], al[4][4];
#pragma unroll
            for (int mi = 0; mi < 4; mi++) {
                uint32_t ad = base + aAddrM + mi * (16 * LDA1) + ko;
                ldsm4(ah[mi], ad);
                ldsm4(al[mi], ad + T1PLANE);
            }
            uint32_t bh[2][4];
#pragma unroll
            for (int nb = 0; nb < 2; nb++) {
                uint32_t bd = base + 2 * T1PLANE + bAddrN + nb * (16 * LDA1) + ko;
                ldsm4(bh[nb], bd);
            }
#pragma unroll
            for (int mi = 0; mi < 4; mi++)
#pragma unroll
                for (int nj = 0; nj < 4; nj++)
                    mma16816h(acc[mi][nj], ah[mi], &bh[nj >> 1][(nj & 1) * 2]);
#pragma unroll
            for (int mi = 0; mi < 4; mi++)
#pragma unroll
                for (int nj = 0; nj < 4; nj++)
                    mma16816h(acc[mi][nj], al[mi], &bh[nj >> 1][(nj & 1) * 2]);
        }
    };

    load_stage(0, 0);
    CP_COMMIT();
    for (int s = 0; s < 4; s++) {
        if (s + 1 < 4) load_stage(s + 1, ((s + 1) & 1) * STG1);
        CP_COMMIT();
        CP_WAIT1();
        __syncthreads();
        compute_stage((s & 1) * STG1);
        __syncthreads();
    }

    float sc[4][2], sh[4][2];
#pragma unroll
    for (int nj = 0; nj < 4; nj++)
#pragma unroll
        for (int q = 0; q < 2; q++) {
            int n = warp_n + nj * 8 + (l & 3) * 2 + q;
            float g = bn1[n], be = bn1[128 + n], mu = bn1[256 + n], va = bn1[384 + n];
            float s = g * rsqrtf(va + EPSV);
            sc[nj][q] = s;
            sh[nj][q] = (b1[n] - mu) * s + be;
        }
#pragma unroll
    for (int mi = 0; mi < 4; mi++)
#pragma unroll
        for (int half = 0; half < 2; half++) {
            int m = m0 + warp_m + mi * 16 + (l >> 2) + half * 8;
            long base = ((long)m * 225 + ij) * 128;
#pragma unroll
            for (int nj = 0; nj < 4; nj++) {
                int n0 = warp_n + nj * 8 + (l & 3) * 2;
                float v0 = fmaxf(fmaf(acc[mi][nj][half * 2 + 0], sc[nj][0], sh[nj][0]), 0.f);
                float v1 = fmaxf(fmaf(acc[mi][nj][half * 2 + 1], sc[nj][1], sh[nj][1]), 0.f);
                uint32_t h, lo;
                split2h(v0, v1, h, lo);
                *(uint32_t*)&g_y1h[base + n0] = h;
                *(uint32_t*)&g_y1l[base + n0] = lo;
            }
        }
}

// ============================================================================
// k2: 7x7 conv MMA fp16 2-term (R15-proven).  M-tile 144, grid 144 (one wave),
// block 288 (9 warps, warp tile 16x128), 4-stage ring (130KB).
// ============================================================================
#define LDA    80
#define A2_V   (144 * 80)
#define B2_V   (128 * 80)
#define STG2   (2 * A2_V + B2_V)       // 33280
#define K2_SMEM (4 * STG2)             // 133120

__global__ __launch_bounds__(288, 1) void k2_mma(
    const float* __restrict__ b2, const float* __restrict__ bn2)
{
    extern __shared__ char smem[];
    const uint32_t sb = smem_u32(smem);
    const int tid = threadIdx.x;
    const int w = tid >> 5, l = tid & 31;
    const int m0 = blockIdx.x * 144;

    const int ar = tid >> 1;
    const int ac = (tid & 1) * 32;
    const int ae = ac >> 1;
    const int gm = m0 + ar;
    const int bv = gm / 81;
    const int pos = gm - bv * 81;
    const int oh = pos / 9, ow = pos - oh * 9;
    const long a_base = ((long)bv * 225 + oh * 15 + ow) * 128;
    const uint32_t dstA = sb + ar * LDA + ac;
    const int br = (tid < 256) ? (tid >> 1) : 0;
    const __half* wf_src = g_w2f + (long)br * 6272;
    const uint32_t dstB = sb + 2 * A2_V + br * LDA + ac;

    float acc[16][4];
#pragma unroll
    for (int i = 0; i < 16; i++)
#pragma unroll
        for (int c = 0; c < 4; c++) acc[i][c] = 0.f;

    auto load_stage = [&](int s, uint32_t off) {
        int g  = s >> 2;
        int kh = g / 7, kw = g - kh * 7;
        long aoff = a_base + (kh * 15 + kw) * 128 + (s & 3) * 32 + ae;
        const __half* pah = g_y1h + aoff;
        const __half* pal = g_y1l + aoff;
        uint32_t dA = dstA + off;
        cpa16(dA, pah);
        cpa16(dA + 16, pah + 8);
        cpa16(dA + A2_V, pal);
        cpa16(dA + A2_V + 16, pal + 8);
        if (tid < 256) {
            long boff = (long)s * 32 + ae;
            uint32_t dB = dstB + off;
            cpa16(dB, wf_src + boff);
            cpa16(dB + 16, wf_src + boff + 8);
        }
    };

    const uint32_t aAddrM = (w * 16 + (l & 15)) * LDA + ((l >> 4) << 4);
    const uint32_t bAddrN = ((l & 7) + ((l >> 4) << 3)) * LDA + (((l >> 3) & 1) << 4);
    auto compute_stage = [&](uint32_t off) {
        uint32_t base = sb + off;
#pragma unroll
        for (int ks = 0; ks < 2; ks++) {
            uint32_t ko = ks * 32;
            uint32_t ah[4], al[4];
            {
                uint32_t ad = base + aAddrM + ko;
                ldsm4(ah, ad);
                ldsm4(al, ad + A2_V);
            }
            uint32_t bh[8][4];
#pragma unroll
            for (int nb = 0; nb < 8; nb++) {
                uint32_t bd = base + 2 * A2_V + bAddrN + nb * (16 * LDA) + ko;
                ldsm4(bh[nb], bd);
            }
#pragma unroll
            for (int nj = 0; nj < 16; nj++)
                mma16816h(acc[nj], ah, &bh[nj >> 1][(nj & 1) * 2]);
#pragma unroll
            for (int nj = 0; nj < 16; nj++)
                mma16816h(acc[nj], al, &bh[nj >> 1][(nj & 1) * 2]);
        }
    };

    load_stage(0, 0);            CP_COMMIT();
    load_stage(1, STG2);         CP_COMMIT();
    load_stage(2, 2 * STG2);     CP_COMMIT();
    for (int s = 0; s < 196; s++) {
        CP_WAIT2();
        __syncthreads();
        compute_stage((s & 3) * STG2);
        if (s + 3 < 196) load_stage(s + 3, ((s + 3) & 3) * STG2);
        CP_COMMIT();
    }

    float sc[16][2], sh[16][2];
#pragma unroll
    for (int nj = 0; nj < 16; nj++)
#pragma unroll
        for (int q = 0; q < 2; q++) {
            int n = nj * 8 + (l & 3) * 2 + q;
            float g = bn2[n], be = bn2[128 + n], mu = bn2[256 + n], va = bn2[384 + n];
            float s = g * rsqrtf(va + EPSV);
            sc[nj][q] = s;
            sh[nj][q] = (b2[n] - mu) * s + be;
        }
#pragma unroll
    for (int half = 0; half < 2; half++) {
        int m = m0 + w * 16 + (l >> 2) + half * 8;
#pragma unroll
        for (int nj = 0; nj < 16; nj++) {
            int n0 = nj * 8 + (l & 3) * 2;
            float v0 = fmaxf(fmaf(acc[nj][half * 2 + 0], sc[nj][0], sh[nj][0]), 0.f);
            float v1 = fmaxf(fmaf(acc[nj][half * 2 + 1], sc[nj][1], sh[nj][1]), 0.f);
            *(float2*)&g_x2f[(long)m * 128 + n0] = make_float2(v0, v1);
            uint32_t h, lo;
            split2h(v0, v1, h, lo);
            *(uint32_t*)&g_a3h[(long)m * 144 + 8 + n0] = h;
            *(uint32_t*)&g_a3l[(long)m * 144 + 8 + n0] = lo;
        }
    }
}

// ============================================================================
// k3: conv1x1 144->128 MMA, fp16 2-term, monolithic smem (3 planes).
// grid 162, block 256.
// ============================================================================
#define LDA3    304
#define T3PLANE (128 * 304)
#define K3_SMEM (3 * T3PLANE)      // 116736

__global__ __launch_bounds__(256) void k3_mma(
    const float* __restrict__ b3, const float* __restrict__ bn3)
{
    extern __shared__ char smem[];
    const uint32_t sb = smem_u32(smem);
    const int tid = threadIdx.x;
    const int w = tid >> 5, l = tid & 31;
    const int m0 = blockIdx.x * 128;
    const int warp_m = (w >> 2) * 64;
    const int warp_n = (w & 3) * 32;

    const int row = tid & 127, half_ = tid >> 7;
    // A: half_ selects plane; full 288B row = 18 cpa16
    const __half* asrc = (half_ ? g_a3l : g_a3h) + (long)(m0 + row) * 144;
    const uint32_t dA = sb + half_ * T3PLANE + row * LDA3;
    // B: single plane; each thread loads half a row (144B = 9 cpa16)
    const __half* bsrc = g_w3f + row * 144;
    const uint32_t dB = sb + 2 * T3PLANE + row * LDA3 + half_ * 144;
#pragma unroll
    for (int j = 0; j < 18; j++) cpa16(dA + j * 16, asrc + j * 8);
#pragma unroll
    for (int j = 0; j < 9; j++)  cpa16(dB + j * 16, bsrc + half_ * 72 + j * 8);
    CP_COMMIT();

    float acc[4][4][4];
#pragma unroll
    for (int i = 0; i < 4; i++)
#pragma unroll
        for (int j = 0; j < 4; j++)
#pragma unroll
            for (int c = 0; c < 4; c++) acc[i][j][c] = 0.f;

    CP_WAIT0();
    __syncthreads();

    const uint32_t aAddrM = (warp_m + (l & 15)) * LDA3 + ((l >> 4) << 4);
    const uint32_t bAddrN = (warp_n + (l & 7) + ((l >> 4) << 3)) * LDA3 + (((l >> 3) & 1) << 4);
#pragma unroll
    for (int ks = 0; ks < 9; ks++) {
        uint32_t ko = ks * 32;
        uint32_t ah[4][4], al[4][4];
#pragma unroll
        for (int mi = 0; mi < 4; mi++) {
            uint32_t ad = sb + aAddrM + mi * (16 * LDA3) + ko;
            ldsm4(ah[mi], ad);
            ldsm4(al[mi], ad + T3PLANE);
        }
        uint32_t bh[2][4];
#pragma unroll
        for (int nb = 0; nb < 2; nb++) {
            uint32_t bd = sb + 2 * T3PLANE + bAddrN + nb * (16 * LDA3) + ko;
            ldsm4(bh[nb], bd);
        }
#pragma unroll
        for (int mi = 0; mi < 4; mi++)
#pragma unroll
            for (int nj = 0; nj < 4; nj++)
                mma16816h(acc[mi][nj], ah[mi], &bh[nj >> 1][(nj & 1) * 2]);
#pragma unroll
        for (int mi = 0; mi < 4; mi++)
#pragma unroll
            for (int nj = 0; nj < 4; nj++)
                mma16816h(acc[mi][nj], al[mi], &bh[nj >> 1][(nj & 1) * 2]);
    }

    float sc[4][2], sh[4][2];
#pragma unroll
    for (int nj = 0; nj < 4; nj++)
#pragma unroll
        for (int q = 0; q < 2; q++) {
            int n = warp_n + nj * 8 + (l & 3) * 2 + q;
            float g = bn3[n], be = bn3[128 + n], mu = bn3[256 + n], va = bn3[384 + n];
            float s = g * rsqrtf(va + EPSV);
            sc[nj][q] = s;
            sh[nj][q] = (b3[n] - mu) * s + be;
        }
#pragma unroll
    for (int mi = 0; mi < 4; mi++)
#pragma unroll
        for (int half = 0; half < 2; half++) {
            int m = m0 + warp_m + mi * 16 + (l >> 2) + half * 8;
#pragma unroll
            for (int nj = 0; nj < 4; nj++) {
                int n0 = warp_n + nj * 8 + (l & 3) * 2;
                float v0 = fmaxf(fmaf(acc[mi][nj][half * 2 + 0], sc[nj][0], sh[nj][0]), 0.f);
                float v1 = fmaxf(fmaf(acc[mi][nj][half * 2 + 1], sc[nj][1], sh[nj][1]), 0.f);
                uint32_t h, lo;
                split2h(v0, v1, h, lo);
                *(uint32_t*)&g_y3h[(long)m * 128 + n0] = h;
                *(uint32_t*)&g_y3l[(long)m * 128 + n0] = lo;
            }
        }
}

// ============================================================================
// k4: conv1x1 128->128 MMA, fp16 2-term, monolithic smem (3 planes)
// -> g_merge fp32 ch-last.  grid 162, block 256.
// ============================================================================
#define LDA4    272
#define T4PLANE (128 * 272)
#define K4_SMEM (3 * T4PLANE)      // 104448

__global__ __launch_bounds__(256) void k4_mma(
    const float* __restrict__ b4, const float* __restrict__ bn4)
{
    extern __shared__ char smem[];
    const uint32_t sb = smem_u32(smem);
    const int tid = threadIdx.x;
    const int w = tid >> 5, l = tid & 31;
    const int m0 = blockIdx.x * 128;
    const int warp_m = (w >> 2) * 64;
    const int warp_n = (w & 3) * 32;

    const int row = tid & 127, half_ = tid >> 7;
    const __half* asrc = (half_ ? g_y3l : g_y3h) + (long)(m0 + row) * 128;
    const uint32_t dA = sb + half_ * T4PLANE + row * LDA4;
    const __half* bsrc = g_w4f + row * 128;
    const uint32_t dB = sb + 2 * T4PLANE + row * LDA4 + half_ * 128;
#pragma unroll
    for (int j = 0; j < 16; j++) cpa16(dA + j * 16, asrc + j * 8);
#pragma unroll
    for (int j = 0; j < 8; j++)  cpa16(dB + j * 16, bsrc + half_ * 64 + j * 8);
    CP_COMMIT();

    float acc[4][4][4];
#pragma unroll
    for (int i = 0; i < 4; i++)
#pragma unroll
        for (int j = 0; j < 4; j++)
#pragma unroll
            for (int c = 0; c < 4; c++) acc[i][j][c] = 0.f;

    CP_WAIT0();
    __syncthreads();

    const uint32_t aAddrM = (warp_m + (l & 15)) * LDA4 + ((l >> 4) << 4);
    const uint32_t bAddrN = (warp_n + (l & 7) + ((l >> 4) << 3)) * LDA4 + (((l >> 3) & 1) << 4);
#pragma unroll
    for (int ks = 0; ks < 8; ks++) {
        uint32_t ko = ks * 32;
        uint32_t ah[4][4], al[4][4];
#pragma unroll
        for (int mi = 0; mi < 4; mi++) {
            uint32_t ad = sb + aAddrM + mi * (16 * LDA4) + ko;
            ldsm4(ah[mi], ad);
            ldsm4(al[mi], ad + T4PLANE);
        }
        uint32_t bh[2][4];
#pragma unroll
        for (int nb = 0; nb < 2; nb++) {
            uint32_t bd = sb + 2 * T4PLANE + bAddrN + nb * (16 * LDA4) + ko;
            ldsm4(bh[nb], bd);
        }
#pragma unroll
        for (int mi = 0; mi < 4; mi++)
#pragma unroll
            for (int nj = 0; nj < 4; nj++)
                mma16816h(acc[mi][nj], ah[mi], &bh[nj >> 1][(nj & 1) * 2]);
#pragma unroll
        for (int mi = 0; mi < 4; mi++)
#pragma unroll
            for (int nj = 0; nj < 4; nj++)
                mma16816h(acc[mi][nj], al[mi], &bh[nj >> 1][(nj & 1) * 2]);
    }

    float sc[4][2], sh[4][2];
#pragma unroll
    for (int nj = 0; nj < 4; nj++)
#pragma unroll
        for (int q = 0; q < 2; q++) {
            int n = warp_n + nj * 8 + (l & 3) * 2 + q;
            float g = bn4[n], be = bn4[128 + n], mu = bn4[256 + n], va = bn4[384 + n];
            float s = g * rsqrtf(va + EPSV);
            sc[nj][q] = s;
            sh[nj][q] = (b4[n] - mu) * s + be;
        }
#pragma unroll
    for (int mi = 0; mi < 4; mi++)
#pragma unroll
        for (int half = 0; half < 2; half++) {
            int m = m0 + warp_m + mi * 16 + (l >> 2) + half * 8;
#pragma unroll
            for (int nj = 0; nj < 4; nj++) {
                int n0 = warp_n + nj * 8 + (l & 3) * 2;
                float v0 = fmaxf(fmaf(acc[mi][nj][half * 2 + 0], sc[nj][0], sh[nj][0]), 0.f);
                float v1 = fmaxf(fmaf(acc[mi][nj][half * 2 + 1], sc[nj][1], sh[nj][1]), 0.f);
                *(float2*)&g_merge[(long)m * 128 + n0] = make_float2(v0, v1);
            }
        }
}

// ============================================================================
// k5: attention logits, wa1 cached in smem.  grid 1296, block 256
// ============================================================================
__global__ __launch_bounds__(256) void k5_logits(
    const float* __restrict__ wa1, const float* __restrict__ ba1,
    const float* __restrict__ bna, const float* __restrict__ wa2,
    const float* __restrict__ ba2)
{
    __shared__ float wa1s[64][129];
    __shared__ float xs[4][128];
    __shared__ float wa2s[64];
    __shared__ float bnsc[64], bnsh[64];
    __shared__ float red[8];
    const int tid = threadIdx.x;
    const int m0 = blockIdx.x * 16;
    const int o  = tid & 63;
    const int mi = tid >> 6;

    for (int i = tid; i < 64 * 128; i += 256)
        wa1s[i >> 7][i & 127] = wa1[i];
    if (tid < 64) {
        float g = bna[tid], be = bna[64 + tid], mu = bna[128 + tid], va = bna[192 + tid];
        float s = g * rsqrtf(va + EPSV);
        bnsc[tid] = s;
        bnsh[tid] = (ba1[tid] - mu) * s + be;
        wa2s[tid] = wa2[tid];
    }
    const float ba2v = ba2[0];
    __syncthreads();

    for (int it = 0; it < 4; it++) {
        {
            int i = tid;
            xs[i >> 7][i & 127] = g_x2f[(long)(m0 + it * 4 + (i >> 7)) * 128 + (i & 127)];
            i += 256;
            xs[i >> 7][i & 127] = g_x2f[(long)(m0 + it * 4 + (i >> 7)) * 128 + (i & 127)];
        }
        __syncthreads();
        float acc = 0.f;
#pragma unroll 8
        for (int c = 0; c < 128; c++) acc = fmaf(wa1s[o][c], xs[mi][c], acc);
        float t = fmaxf(fmaf(acc, bnsc[o], bnsh[o]), 0.f);
        float p = wa2s[o] * t;
#pragma unroll
        for (int off = 16; off > 0; off >>= 1) p += __shfl_down_sync(0xffffffffu, p, off);
        if ((tid & 31) == 0) red[tid >> 5] = p;
        __syncthreads();
        if (o == 0) g_logits[m0 + it * 4 + mi] = red[mi * 2] + red[mi * 2 + 1] + ba2v;
        __syncthreads();
    }
}

// ============================================================================
// k6: softmax(81) + attention-pool + final linear (128->6).  grid 256, block 128
// ============================================================================
__global__ __launch_bounds__(128) void k6_final(
    const float* __restrict__ wl, const float* __restrict__ bl,
    float* __restrict__ out)
{
    __shared__ float att[81];
    __shared__ float pooled[128];
    __shared__ float red[4];
    const int b = blockIdx.x;
    const int t = threadIdx.x;

    float v = (t < 81) ? g_logits[b * 81 + t] : -1e30f;
    float mx = v;
#pragma unroll
    for (int off = 16; off > 0; off >>= 1) mx = fmaxf(mx, __shfl_xor_sync(0xffffffffu, mx, off));
    if ((t & 31) == 0) red[t >> 5] = mx;
    __syncthreads();
    mx = fmaxf(fmaxf(red[0], red[1]), fmaxf(red[2], red[3]));
    float e = (t < 81) ? expf(v - mx) : 0.f;
    __syncthreads();
    float sm = e;
#pragma unroll
    for (int off = 16; off > 0; off >>= 1) sm += __shfl_xor_sync(0xffffffffu, sm, off);
    if ((t & 31) == 0) red[t >> 5] = sm;
    __syncthreads();
    sm = red[0] + red[1] + red[2] + red[3];
    if (t < 81) att[t] = e / sm;
    __syncthreads();

    float acc = 0.f;
    const float* mr = g_merge + (long)b * 81 * 128 + t;
#pragma unroll 9
    for (int p = 0; p < 81; p++) acc = fmaf(att[p], mr[p * 128], acc);
    pooled[t] = acc;
    __syncthreads();

    if (t < 6) {
        float s2 = bl[t];
        const float* wr = wl + t * 128;
#pragma unroll 8
        for (int o = 0; o < 128; o++) s2 = fmaf(wr[o], pooled[o], s2);
        out[b * 6 + t] = s2;
    }
}

// ============================================================================
extern "C" void kernel_launch(void* const* d_in, const int* in_sizes, int n_in,
                              void* d_out, int out_size)
{
    const float* x    = (const float*)d_in[0];
    const float* w1   = (const float*)d_in[1];
    const float* b1   = (const float*)d_in[2];
    const float* bn1  = (const float*)d_in[3];
    const float* w2   = (const float*)d_in[4];
    const float* b2   = (const float*)d_in[5];
    const float* bn2  = (const float*)d_in[6];
    const float* wgt  = (const float*)d_in[7];
    const float* w3   = (const float*)d_in[8];
    const float* b3   = (const float*)d_in[9];
    const float* bn3  = (const float*)d_in[10];
    const float* w4   = (const float*)d_in[11];
    const float* b4   = (const float*)d_in[12];
    const float* bn4  = (const float*)d_in[13];
    const float* wa1  = (const float*)d_in[14];
    const float* ba1  = (const float*)d_in[15];
    const float* bna  = (const float*)d_in[16];
    const float* wa2  = (const float*)d_in[17];
    const float* ba2  = (const float*)d_in[18];
    const float* wl   = (const float*)d_in[19];
    const float* bl   = (const float*)d_in[20];
    float* out = (float*)d_out;

    cudaFuncSetAttribute(k1_mma, cudaFuncAttributeMaxDynamicSharedMemorySize, K1_SMEM);
    cudaFuncSetAttribute(k2_mma, cudaFuncAttributeMaxDynamicSharedMemorySize, K2_SMEM);
    cudaFuncSetAttribute(k3_mma, cudaFuncAttributeMaxDynamicSharedMemorySize, K3_SMEM);
    cudaFuncSetAttribute(k4_mma, cudaFuncAttributeMaxDynamicSharedMemorySize, K4_SMEM);

    // launch order keeps k2_mma in ncu's sampled slot (4th launch)
    prepA<<<30848, 256>>>(x, w1);                  // 1
    dim3 g1(225, 2);
    k1_mma<<<g1, 256, K1_SMEM>>>(b1, bn1);         // 2
    prepB<<<4568, 256>>>(w2, w3, w4, wgt);         // 3
    k2_mma<<<144, 288, K2_SMEM>>>(b2, bn2);        // 4  <-- profiled, one wave
    k3_mma<<<162, 256, K3_SMEM>>>(b3, bn3);        // 5
    k4_mma<<<162, 256, K4_SMEM>>>(b4, bn4);        // 6
    k5_logits<<<1296, 256>>>(wa1, ba1, bna, wa2, ba2); // 7
    k6_final<<<256, 128>>>(wl, bl, out);           // 8
}

// round 17
// speedup vs baseline: 1.5682x; 1.0273x over previous
#include <cuda_runtime.h>
#include <cuda_bf16.h>
#include <cuda_fp16.h>
#include <cstdint>

#define EPSV 1e-5f

typedef unsigned long long ull;

// ---------------- scratch buffers (static, allocation-free) ----------------
__device__ __half g_xth[225 * 256 * 256];  // x transposed+split fp16: [ij][m][ck<=255]
__device__ __half g_xtl[225 * 256 * 256];
__device__ __half g_B1f[225 * 128 * 256];  // per-ij conv1 B, single fp16
__device__ __half g_y1h[256 * 225 * 128];  // y1 fp16 split, ch-last (m, sp, c)
__device__ __half g_y1l[256 * 225 * 128];
__device__ __half g_w2f[128 * 6272];       // w2 single fp16: [n][(kh*7+kw)*128+ci]
__device__ float  g_x2f[20736 * 128];      // x_ fp32 ch-last [m][c] (for k5)
__device__ __half g_a3h[20736 * 144];      // k3 A operand fp16 split: [m][144]
__device__ __half g_a3l[20736 * 144];
__device__ __half g_w3f[128 * 144];        // w3 single fp16 (padded cols)
__device__ __half g_y3h[20736 * 128];
__device__ __half g_y3l[20736 * 128];
__device__ __half g_w4f[128 * 128];        // w4 single fp16
__device__ float  g_merge[20736 * 128];    // fp32 ch-last [m][c]
__device__ float  g_logits[20736];

// ---------------- PTX helpers (baseline sm_80+) ----------------
__device__ __forceinline__ uint32_t smem_u32(const void* p) {
    uint32_t a;
    asm("{ .reg .u64 t; cvta.to.shared.u64 t, %1; cvt.u32.u64 %0, t; }" : "=r"(a) : "l"(p));
    return a;
}
__device__ __forceinline__ void cpa16(uint32_t dst, const void* src) {
    asm volatile("cp.async.ca.shared.global [%0], [%1], 16;" :: "r"(dst), "l"(src));
}
#define CP_COMMIT() asm volatile("cp.async.commit_group;" ::: "memory")
#define CP_WAIT2()  asm volatile("cp.async.wait_group 2;" ::: "memory")
#define CP_WAIT1()  asm volatile("cp.async.wait_group 1;" ::: "memory")
#define CP_WAIT0()  asm volatile("cp.async.wait_group 0;" ::: "memory")

__device__ __forceinline__ void ldsm4(uint32_t* r, uint32_t addr) {
    asm volatile("ldmatrix.sync.aligned.m8n8.x4.shared.b16 {%0,%1,%2,%3}, [%4];"
                 : "=r"(r[0]), "=r"(r[1]), "=r"(r[2]), "=r"(r[3]) : "r"(addr));
}
// fp16 MMA
__device__ __forceinline__ void mma16816h(float* d, const uint32_t* a, const uint32_t* b) {
    asm volatile(
        "mma.sync.aligned.m16n8k16.row.col.f32.f16.f16.f32 "
        "{%0,%1,%2,%3}, {%4,%5,%6,%7}, {%8,%9}, {%0,%1,%2,%3};"
        : "+f"(d[0]), "+f"(d[1]), "+f"(d[2]), "+f"(d[3])
        : "r"(a[0]), "r"(a[1]), "r"(a[2]), "r"(a[3]), "r"(b[0]), "r"(b[1]));
}
__device__ __forceinline__ uint32_t cvt2h(float f0, float f1) {         // f16x2, lo=f0
    uint32_t r;
    asm("cvt.rn.f16x2.f32 %0, %1, %2;" : "=r"(r) : "f"(f1), "f"(f0));
    return r;
}
__device__ __forceinline__ void split2h(float v0, float v1, uint32_t& h, uint32_t& lo) {
    h = cvt2h(v0, v1);
    float h0 = __half2float(__ushort_as_half((unsigned short)(h & 0xFFFFu)));
    float h1 = __half2float(__ushort_as_half((unsigned short)(h >> 16)));
    lo = cvt2h(v0 - h0, v1 - h1);
}

// ============================================================================
// prepA: merged kX (x transpose + fp16 split) + kB (per-ij B1, single fp16)
// ============================================================================
__global__ __launch_bounds__(256) void prepA(const float* __restrict__ x,
                                             const float* __restrict__ w1)
{
    const int b = blockIdx.x;
    if (b < 2048) {
        __shared__ float s[225][33];
        const int tid = threadIdx.x;
        const int tx = tid & 31, ty = tid >> 5;
        const int ij0 = (b & 7) * 32;
        const int m   = b >> 3;
        const int nij = (ij0 + 32 <= 225) ? 32 : (225 - ij0);

        const float* xp = x + (long)m * 50625;
        for (int cc = 0; cc < 29; cc++) {
            int c = cc * 8 + ty;
            if (c < 225) {
                float v = (tx < nij) ? xp[c * 225 + ij0 + tx] : 0.f;
                s[c][tx] = v;
            }
        }
        __syncthreads();
        for (int ii = 0; ii < nij; ii++) {
            float v = (tid < 225) ? s[tid][ii] : 0.f;
            __half h = __float2half(v);
            long idx = ((long)(ij0 + ii) * 256 + m) * 256 + tid;
            g_xth[idx] = h;
            g_xtl[idx] = __float2half(v - __half2float(h));
        }
    } else {
        const int bid = b - 2048;
        const int ij = bid >> 7, n = bid & 127;
        const int ip = ij / 15, jp = ij - ip * 15;
        const int k = threadIdx.x;
        float v = 0.f;
        if (k < 225) {
            int a = k / 15, bb = k - a * 15;
            v = w1[n * 841 + (a + 14 - ip) * 29 + (bb + 14 - jp)];
        }
        g_B1f[((long)ij * 128 + n) * 256 + k] = __float2half(v);
    }
}

// ============================================================================
// prepB: merged w2/w3/w4 (single fp16) + kF (a3 cols, fp16 split)
// ============================================================================
__global__ __launch_bounds__(256) void prepB(const float* __restrict__ w2,
                                             const float* __restrict__ w3,
                                             const float* __restrict__ w4,
                                             const float* __restrict__ wgt)
{
    const int b = blockIdx.x;
    if (b < 3136) {
        int t = b * 256 + threadIdx.x;
        if (t < 128 * 6272) {
            int n = t / 6272, k = t - n * 6272;
            int g = k >> 7, ci = k & 127;
            g_w2f[t] = __float2half(w2[n * 6272 + ci * 49 + g]);
        }
    } else if (b < 3136 + 72) {
        int t = (b - 3136) * 256 + threadIdx.x;
        if (t < 128 * 144) {
            int n = t / 144, j = t - n * 144;
            float v = 0.f;
            if (j < 5)                  v = w3[n * 133 + j];
            else if (j >= 8 && j < 136) v = w3[n * 133 + j - 3];
            g_w3f[t] = __float2half(v);
        }
    } else if (b < 3136 + 72 + 64) {
        int t = (b - 3136 - 72) * 256 + threadIdx.x;
        if (t < 128 * 128) g_w4f[t] = __float2half(w4[t]);
    } else {
        int t = (b - 3136 - 72 - 64) * 256 + threadIdx.x;
        if (t < 20736 * 16) {
            int m = t >> 4, jj = t & 15;
            int j = (jj < 8) ? jj : (128 + jj);
            float v = (j < 5) ? wgt[j * 81 + (m % 81)] : 0.f;
            __half h = __float2half(v);
            long idx = (long)m * 144 + j;
            g_a3h[idx] = h;
            g_a3l[idx] = __float2half(v - __half2float(h));
        }
    }
}

// ============================================================================
// k1: align-conv1 MMA, fp16 2-term.  per ij: M=256, N=128, K=256(padded).
// grid (225, 2), block 256.  4 stages KT=64, 3 planes, 110KB.
// ============================================================================
#define LDA1    144
#define T1PLANE (128 * 144)
#define STG1    (3 * T1PLANE)
#define K1_SMEM (2 * STG1)         // 110592

__global__ __launch_bounds__(256) void k1_mma(
    const float* __restrict__ b1, const float* __restrict__ bn1)
{
    extern __shared__ char smem[];
    const uint32_t sb = smem_u32(smem);
    const int tid = threadIdx.x;
    const int w = tid >> 5, l = tid & 31;
    const int ij = blockIdx.x;
    const int m0 = blockIdx.y * 128;
    const int warp_m = (w >> 2) * 64;
    const int warp_n = (w & 3) * 32;

    const int row = tid & 127, half_ = tid >> 7;
    const __half* asrc = (half_ ? g_xtl : g_xth) + ((long)ij * 256 + m0 + row) * 256;
    const uint32_t dA = sb + half_ * T1PLANE + row * LDA1;
    const __half* bsrc = g_B1f + ((long)ij * 128 + row) * 256;
    const uint32_t dB = sb + 2 * T1PLANE + row * LDA1 + half_ * 64;

    float acc[4][4][4];
#pragma unroll
    for (int i = 0; i < 4; i++)
#pragma unroll
        for (int j = 0; j < 4; j++)
#pragma unroll
            for (int c = 0; c < 4; c++) acc[i][j][c] = 0.f;

    auto load_stage = [&](int s, uint32_t off) {
#pragma unroll
        for (int j = 0; j < 8; j++)
            cpa16(dA + off + j * 16, asrc + s * 64 + j * 8);
#pragma unroll
        for (int j = 0; j < 4; j++)
            cpa16(dB + off + j * 16, bsrc + s * 64 + half_ * 32 + j * 8);
    };

    const uint32_t aAddrM = (warp_m + (l & 15)) * LDA1 + ((l >> 4) << 4);
    const uint32_t bAddrN = (warp_n + (l & 7) + ((l >> 4) << 3)) * LDA1 + (((l >> 3) & 1) << 4);
    auto compute_stage = [&](uint32_t off) {
        uint32_t base = sb + off;
#pragma unroll
        for (int ks = 0; ks < 4; ks++) {
            uint32_t ko = ks * 32;
            uint32_t ah[4][4], al[4][4];
#pragma unroll
            for (int mi = 0; mi < 4; mi++) {
                uint32_t ad = base + aAddrM + mi * (16 * LDA1) + ko;
                ldsm4(ah[mi], ad);
                ldsm4(al[mi], ad + T1PLANE);
            }
            uint32_t bh[2][4];
#pragma unroll
            for (int nb = 0; nb < 2; nb++) {
                uint32_t bd = base + 2 * T1PLANE + bAddrN + nb * (16 * LDA1) + ko;
                ldsm4(bh[nb], bd);
            }
#pragma unroll
            for (int mi = 0; mi < 4; mi++)
#pragma unroll
                for (int nj = 0; nj < 4; nj++)
                    mma16816h(acc[mi][nj], ah[mi], &bh[nj >> 1][(nj & 1) * 2]);
#pragma unroll
            for (int mi = 0; mi < 4; mi++)
#pragma unroll
                for (int nj = 0; nj < 4; nj++)
                    mma16816h(acc[mi][nj], al[mi], &bh[nj >> 1][(nj & 1) * 2]);
        }
    };

    load_stage(0, 0);
    CP_COMMIT();
    for (int s = 0; s < 4; s++) {
        if (s + 1 < 4) load_stage(s + 1, ((s + 1) & 1) * STG1);
        CP_COMMIT();
        CP_WAIT1();
        __syncthreads();
        compute_stage((s & 1) * STG1);
        __syncthreads();
    }

    float sc[4][2], sh[4][2];
#pragma unroll
    for (int nj = 0; nj < 4; nj++)
#pragma unroll
        for (int q = 0; q < 2; q++) {
            int n = warp_n + nj * 8 + (l & 3) * 2 + q;
            float g = bn1[n], be = bn1[128 + n], mu = bn1[256 + n], va = bn1[384 + n];
            float s = g * rsqrtf(va + EPSV);
            sc[nj][q] = s;
            sh[nj][q] = (b1[n] - mu) * s + be;
        }
#pragma unroll
    for (int mi = 0; mi < 4; mi++)
#pragma unroll
        for (int half = 0; half < 2; half++) {
            int m = m0 + warp_m + mi * 16 + (l >> 2) + half * 8;
            long base = ((long)m * 225 + ij) * 128;
#pragma unroll
            for (int nj = 0; nj < 4; nj++) {
                int n0 = warp_n + nj * 8 + (l & 3) * 2;
                float v0 = fmaxf(fmaf(acc[mi][nj][half * 2 + 0], sc[nj][0], sh[nj][0]), 0.f);
                float v1 = fmaxf(fmaf(acc[mi][nj][half * 2 + 1], sc[nj][1], sh[nj][1]), 0.f);
                uint32_t h, lo;
                split2h(v0, v1, h, lo);
                *(uint32_t*)&g_y1h[base + n0] = h;
                *(uint32_t*)&g_y1l[base + n0] = lo;
            }
        }
}

// ============================================================================
// k2: 7x7 conv MMA fp16 2-term, RETILED for B reuse: 6 warps (3x2 grid),
// warp tile 48x64, block 192.  M-tile 144, grid 144 (one wave), 4-stage ring.
// LDSM/stage: 120 (was 180) at same 576 MMA/stage.
// ============================================================================
#define LDA    80
#define A2_V   (144 * 80)
#define B2_V   (128 * 80)
#define STG2   (2 * A2_V + B2_V)       // 33280
#define K2_SMEM (4 * STG2)             // 133120

__global__ __launch_bounds__(192, 1) void k2_mma(
    const float* __restrict__ b2, const float* __restrict__ bn2)
{
    extern __shared__ char smem[];
    const uint32_t sb = smem_u32(smem);
    const int tid = threadIdx.x;
    const int w = tid >> 5, l = tid & 31;   // 6 warps
    const int m0 = blockIdx.x * 144;
    const int warp_m = (w >> 1) * 48;       // 3 rows of warps
    const int warp_n = (w & 1) * 64;        // 2 cols of warps

    // ---- A loader: 576 16B-chunks per plane, thread covers 3 fixed chunks ----
    // chunk c: row = c>>2, byte-in-row = (c&3)*16
    int a_row[3], a_cb[3];
    long a_base[3];
#pragma unroll
    for (int j = 0; j < 3; j++) {
        int c = tid + j * 192;
        a_row[j] = c >> 2;
        a_cb[j]  = (c & 3) * 16;
        int gm = m0 + a_row[j];
        int bv = gm / 81;
        int pos = gm - bv * 81;
        int oh = pos / 9, ow = pos - oh * 9;
        a_base[j] = ((long)bv * 225 + oh * 15 + ow) * 128 + (a_cb[j] >> 1);
    }

    float acc[3][8][4];
#pragma unroll
    for (int i = 0; i < 3; i++)
#pragma unroll
        for (int j = 0; j < 8; j++)
#pragma unroll
            for (int c = 0; c < 4; c++) acc[i][j][c] = 0.f;

    auto load_stage = [&](int s, uint32_t off) {
        int g  = s >> 2;
        int kh = g / 7, kw = g - kh * 7;
        long soff = (kh * 15 + kw) * 128 + (s & 3) * 32;
#pragma unroll
        for (int j = 0; j < 3; j++) {
            long aoff = a_base[j] + soff;
            uint32_t dA = sb + off + a_row[j] * LDA + a_cb[j];
            cpa16(dA, g_y1h + aoff);
            cpa16(dA + A2_V, g_y1l + aoff);
        }
        // B: 512 chunks by 192 threads
        for (int i = tid; i < 512; i += 192) {
            int r = i >> 2, cb = (i & 3) * 16;
            cpa16(sb + off + 2 * A2_V + r * LDA + cb,
                  g_w2f + (long)r * 6272 + s * 32 + (cb >> 1));
        }
    };

    const uint32_t aAddrM = (warp_m + (l & 15)) * LDA + ((l >> 4) << 4);
    const uint32_t bAddrN = (warp_n + (l & 7) + ((l >> 4) << 3)) * LDA + (((l >> 3) & 1) << 4);
    auto compute_stage = [&](uint32_t off) {
        uint32_t base = sb + off;
#pragma unroll
        for (int ks = 0; ks < 2; ks++) {
            uint32_t ko = ks * 32;
            uint32_t ah[3][4], al[3][4];
#pragma unroll
            for (int mi = 0; mi < 3; mi++) {
                uint32_t ad = base + aAddrM + mi * (16 * LDA) + ko;
                ldsm4(ah[mi], ad);
                ldsm4(al[mi], ad + A2_V);
            }
            uint32_t bh[4][4];
#pragma unroll
            for (int nb = 0; nb < 4; nb++) {
                uint32_t bd = base + 2 * A2_V + bAddrN + nb * (16 * LDA) + ko;
                ldsm4(bh[nb], bd);
            }
#pragma unroll
            for (int mi = 0; mi < 3; mi++)
#pragma unroll
                for (int nj = 0; nj < 8; nj++)
                    mma16816h(acc[mi][nj], ah[mi], &bh[nj >> 1][(nj & 1) * 2]);
#pragma unroll
            for (int mi = 0; mi < 3; mi++)
#pragma unroll
                for (int nj = 0; nj < 8; nj++)
                    mma16816h(acc[mi][nj], al[mi], &bh[nj >> 1][(nj & 1) * 2]);
        }
    };

    load_stage(0, 0);            CP_COMMIT();
    load_stage(1, STG2);         CP_COMMIT();
    load_stage(2, 2 * STG2);     CP_COMMIT();
    for (int s = 0; s < 196; s++) {
        CP_WAIT2();
        __syncthreads();
        compute_stage((s & 3) * STG2);
        if (s + 3 < 196) load_stage(s + 3, ((s + 3) & 3) * STG2);
        CP_COMMIT();
    }

    float sc[8][2], sh[8][2];
#pragma unroll
    for (int nj = 0; nj < 8; nj++)
#pragma unroll
        for (int q = 0; q < 2; q++) {
            int n = warp_n + nj * 8 + (l & 3) * 2 + q;
            float g = bn2[n], be = bn2[128 + n], mu = bn2[256 + n], va = bn2[384 + n];
            float s = g * rsqrtf(va + EPSV);
            sc[nj][q] = s;
            sh[nj][q] = (b2[n] - mu) * s + be;
        }
#pragma unroll
    for (int mi = 0; mi < 3; mi++)
#pragma unroll
        for (int half = 0; half < 2; half++) {
            int m = m0 + warp_m + mi * 16 + (l >> 2) + half * 8;
#pragma unroll
            for (int nj = 0; nj < 8; nj++) {
                int n0 = warp_n + nj * 8 + (l & 3) * 2;
                float v0 = fmaxf(fmaf(acc[mi][nj][half * 2 + 0], sc[nj][0], sh[nj][0]), 0.f);
                float v1 = fmaxf(fmaf(acc[mi][nj][half * 2 + 1], sc[nj][1], sh[nj][1]), 0.f);
                *(float2*)&g_x2f[(long)m * 128 + n0] = make_float2(v0, v1);
                uint32_t h, lo;
                split2h(v0, v1, h, lo);
                *(uint32_t*)&g_a3h[(long)m * 144 + 8 + n0] = h;
                *(uint32_t*)&g_a3l[(long)m * 144 + 8 + n0] = lo;
            }
        }
}

// ============================================================================
// k3: conv1x1 144->128 MMA, fp16 2-term, monolithic smem (3 planes).
// grid 162, block 256.
// ============================================================================
#define LDA3    304
#define T3PLANE (128 * 304)
#define K3_SMEM (3 * T3PLANE)      // 116736

__global__ __launch_bounds__(256) void k3_mma(
    const float* __restrict__ b3, const float* __restrict__ bn3)
{
    extern __shared__ char smem[];
    const uint32_t sb = smem_u32(smem);
    const int tid = threadIdx.x;
    const int w = tid >> 5, l = tid & 31;
    const int m0 = blockIdx.x * 128;
    const int warp_m = (w >> 2) * 64;
    const int warp_n = (w & 3) * 32;

    const int row = tid & 127, half_ = tid >> 7;
    const __half* asrc = (half_ ? g_a3l : g_a3h) + (long)(m0 + row) * 144;
    const uint32_t dA = sb + half_ * T3PLANE + row * LDA3;
    const __half* bsrc = g_w3f + row * 144;
    const uint32_t dB = sb + 2 * T3PLANE + row * LDA3 + half_ * 144;
#pragma unroll
    for (int j = 0; j < 18; j++) cpa16(dA + j * 16, asrc + j * 8);
#pragma unroll
    for (int j = 0; j < 9; j++)  cpa16(dB + j * 16, bsrc + half_ * 72 + j * 8);
    CP_COMMIT();

    float acc[4][4][4];
#pragma unroll
    for (int i = 0; i < 4; i++)
#pragma unroll
        for (int j = 0; j < 4; j++)
#pragma unroll
            for (int c = 0; c < 4; c++) acc[i][j][c] = 0.f;

    CP_WAIT0();
    __syncthreads();

    const uint32_t aAddrM = (warp_m + (l & 15)) * LDA3 + ((l >> 4) << 4);
    const uint32_t bAddrN = (warp_n + (l & 7) + ((l >> 4) << 3)) * LDA3 + (((l >> 3) & 1) << 4);
#pragma unroll
    for (int ks = 0; ks < 9; ks++) {
        uint32_t ko = ks * 32;
        uint32_t ah[4][4], al[4][4];
#pragma unroll
        for (int mi = 0; mi < 4; mi++) {
            uint32_t ad = sb + aAddrM + mi * (16 * LDA3) + ko;
            ldsm4(ah[mi], ad);
            ldsm4(al[mi], ad + T3PLANE);
        }
        uint32_t bh[2][4];
#pragma unroll
        for (int nb = 0; nb < 2; nb++) {
            uint32_t bd = sb + 2 * T3PLANE + bAddrN + nb * (16 * LDA3) + ko;
            ldsm4(bh[nb], bd);
        }
#pragma unroll
        for (int mi = 0; mi < 4; mi++)
#pragma unroll
            for (int nj = 0; nj < 4; nj++)
                mma16816h(acc[mi][nj], ah[mi], &bh[nj >> 1][(nj & 1) * 2]);
#pragma unroll
        for (int mi = 0; mi < 4; mi++)
#pragma unroll
            for (int nj = 0; nj < 4; nj++)
                mma16816h(acc[mi][nj], al[mi], &bh[nj >> 1][(nj & 1) * 2]);
    }

    float sc[4][2], sh[4][2];
#pragma unroll
    for (int nj = 0; nj < 4; nj++)
#pragma unroll
        for (int q = 0; q < 2; q++) {
            int n = warp_n + nj * 8 + (l & 3) * 2 + q;
            float g = bn3[n], be = bn3[128 + n], mu = bn3[256 + n], va = bn3[384 + n];
            float s = g * rsqrtf(va + EPSV);
            sc[nj][q] = s;
            sh[nj][q] = (b3[n] - mu) * s + be;
        }
#pragma unroll
    for (int mi = 0; mi < 4; mi++)
#pragma unroll
        for (int half = 0; half < 2; half++) {
            int m = m0 + warp_m + mi * 16 + (l >> 2) + half * 8;
#pragma unroll
            for (int nj = 0; nj < 4; nj++) {
                int n0 = warp_n + nj * 8 + (l & 3) * 2;
                float v0 = fmaxf(fmaf(acc[mi][nj][half * 2 + 0], sc[nj][0], sh[nj][0]), 0.f);
                float v1 = fmaxf(fmaf(acc[mi][nj][half * 2 + 1], sc[nj][1], sh[nj][1]), 0.f);
                uint32_t h, lo;
                split2h(v0, v1, h, lo);
                *(uint32_t*)&g_y3h[(long)m * 128 + n0] = h;
                *(uint32_t*)&g_y3l[(long)m * 128 + n0] = lo;
            }
        }
}

// ============================================================================
// k4: conv1x1 128->128 MMA, fp16 2-term, monolithic smem (3 planes)
// -> g_merge fp32 ch-last.  grid 162, block 256.
// ============================================================================
#define LDA4    272
#define T4PLANE (128 * 272)
#define K4_SMEM (3 * T4PLANE)      // 104448

__global__ __launch_bounds__(256) void k4_mma(
    const float* __restrict__ b4, const float* __restrict__ bn4)
{
    extern __shared__ char smem[];
    const uint32_t sb = smem_u32(smem);
    const int tid = threadIdx.x;
    const int w = tid >> 5, l = tid & 31;
    const int m0 = blockIdx.x * 128;
    const int warp_m = (w >> 2) * 64;
    const int warp_n = (w & 3) * 32;

    const int row = tid & 127, half_ = tid >> 7;
    const __half* asrc = (half_ ? g_y3l : g_y3h) + (long)(m0 + row) * 128;
    const uint32_t dA = sb + half_ * T4PLANE + row * LDA4;
    const __half* bsrc = g_w4f + row * 128;
    const uint32_t dB = sb + 2 * T4PLANE + row * LDA4 + half_ * 128;
#pragma unroll
    for (int j = 0; j < 16; j++) cpa16(dA + j * 16, asrc + j * 8);
#pragma unroll
    for (int j = 0; j < 8; j++)  cpa16(dB + j * 16, bsrc + half_ * 64 + j * 8);
    CP_COMMIT();

    float acc[4][4][4];
#pragma unroll
    for (int i = 0; i < 4; i++)
#pragma unroll
        for (int j = 0; j < 4; j++)
#pragma unroll
            for (int c = 0; c < 4; c++) acc[i][j][c] = 0.f;

    CP_WAIT0();
    __syncthreads();

    const uint32_t aAddrM = (warp_m + (l & 15)) * LDA4 + ((l >> 4) << 4);
    const uint32_t bAddrN = (warp_n + (l & 7) + ((l >> 4) << 3)) * LDA4 + (((l >> 3) & 1) << 4);
#pragma unroll
    for (int ks = 0; ks < 8; ks++) {
        uint32_t ko = ks * 32;
        uint32_t ah[4][4], al[4][4];
#pragma unroll
        for (int mi = 0; mi < 4; mi++) {
            uint32_t ad = sb + aAddrM + mi * (16 * LDA4) + ko;
            ldsm4(ah[mi], ad);
            ldsm4(al[mi], ad + T4PLANE);
        }
        uint32_t bh[2][4];
#pragma unroll
        for (int nb = 0; nb < 2; nb++) {
            uint32_t bd = sb + 2 * T4PLANE + bAddrN + nb * (16 * LDA4) + ko;
            ldsm4(bh[nb], bd);
        }
#pragma unroll
        for (int mi = 0; mi < 4; mi++)
#pragma unroll
            for (int nj = 0; nj < 4; nj++)
                mma16816h(acc[mi][nj], ah[mi], &bh[nj >> 1][(nj & 1) * 2]);
#pragma unroll
        for (int mi = 0; mi < 4; mi++)
#pragma unroll
            for (int nj = 0; nj < 4; nj++)
                mma16816h(acc[mi][nj], al[mi], &bh[nj >> 1][(nj & 1) * 2]);
    }

    float sc[4][2], sh[4][2];
#pragma unroll
    for (int nj = 0; nj < 4; nj++)
#pragma unroll
        for (int q = 0; q < 2; q++) {
            int n = warp_n + nj * 8 + (l & 3) * 2 + q;
            float g = bn4[n], be = bn4[128 + n], mu = bn4[256 + n], va = bn4[384 + n];
            float s = g * rsqrtf(va + EPSV);
            sc[nj][q] = s;
            sh[nj][q] = (b4[n] - mu) * s + be;
        }
#pragma unroll
    for (int mi = 0; mi < 4; mi++)
#pragma unroll
        for (int half = 0; half < 2; half++) {
            int m = m0 + warp_m + mi * 16 + (l >> 2) + half * 8;
#pragma unroll
            for (int nj = 0; nj < 4; nj++) {
                int n0 = warp_n + nj * 8 + (l & 3) * 2;
                float v0 = fmaxf(fmaf(acc[mi][nj][half * 2 + 0], sc[nj][0], sh[nj][0]), 0.f);
                float v1 = fmaxf(fmaf(acc[mi][nj][half * 2 + 1], sc[nj][1], sh[nj][1]), 0.f);
                *(float2*)&g_merge[(long)m * 128 + n0] = make_float2(v0, v1);
            }
        }
}

// ============================================================================
// k5: attention logits, wa1 cached in smem.  grid 1296, block 256
// ============================================================================
__global__ __launch_bounds__(256) void k5_logits(
    const float* __restrict__ wa1, const float* __restrict__ ba1,
    const float* __restrict__ bna, const float* __restrict__ wa2,
    const float* __restrict__ ba2)
{
    __shared__ float wa1s[64][129];
    __shared__ float xs[4][128];
    __shared__ float wa2s[64];
    __shared__ float bnsc[64], bnsh[64];
    __shared__ float red[8];
    const int tid = threadIdx.x;
    const int m0 = blockIdx.x * 16;
    const int o  = tid & 63;
    const int mi = tid >> 6;

    for (int i = tid; i < 64 * 128; i += 256)
        wa1s[i >> 7][i & 127] = wa1[i];
    if (tid < 64) {
        float g = bna[tid], be = bna[64 + tid], mu = bna[128 + tid], va = bna[192 + tid];
        float s = g * rsqrtf(va + EPSV);
        bnsc[tid] = s;
        bnsh[tid] = (ba1[tid] - mu) * s + be;
        wa2s[tid] = wa2[tid];
    }
    const float ba2v = ba2[0];
    __syncthreads();

    for (int it = 0; it < 4; it++) {
        {
            int i = tid;
            xs[i >> 7][i & 127] = g_x2f[(long)(m0 + it * 4 + (i >> 7)) * 128 + (i & 127)];
            i += 256;
            xs[i >> 7][i & 127] = g_x2f[(long)(m0 + it * 4 + (i >> 7)) * 128 + (i & 127)];
        }
        __syncthreads();
        float acc = 0.f;
#pragma unroll 8
        for (int c = 0; c < 128; c++) acc = fmaf(wa1s[o][c], xs[mi][c], acc);
        float t = fmaxf(fmaf(acc, bnsc[o], bnsh[o]), 0.f);
        float p = wa2s[o] * t;
#pragma unroll
        for (int off = 16; off > 0; off >>= 1) p += __shfl_down_sync(0xffffffffu, p, off);
        if ((tid & 31) == 0) red[tid >> 5] = p;
        __syncthreads();
        if (o == 0) g_logits[m0 + it * 4 + mi] = red[mi * 2] + red[mi * 2 + 1] + ba2v;
        __syncthreads();
    }
}

// ============================================================================
// k6: softmax(81) + attention-pool + final linear (128->6).  grid 256, block 128
// ============================================================================
__global__ __launch_bounds__(128) void k6_final(
    const float* __restrict__ wl, const float* __restrict__ bl,
    float* __restrict__ out)
{
    __shared__ float att[81];
    __shared__ float pooled[128];
    __shared__ float red[4];
    const int b = blockIdx.x;
    const int t = threadIdx.x;

    float v = (t < 81) ? g_logits[b * 81 + t] : -1e30f;
    float mx = v;
#pragma unroll
    for (int off = 16; off > 0; off >>= 1) mx = fmaxf(mx, __shfl_xor_sync(0xffffffffu, mx, off));
    if ((t & 31) == 0) red[t >> 5] = mx;
    __syncthreads();
    mx = fmaxf(fmaxf(red[0], red[1]), fmaxf(red[2], red[3]));
    float e = (t < 81) ? expf(v - mx) : 0.f;
    __syncthreads();
    float sm = e;
#pragma unroll
    for (int off = 16; off > 0; off >>= 1) sm += __shfl_xor_sync(0xffffffffu, sm, off);
    if ((t & 31) == 0) red[t >> 5] = sm;
    __syncthreads();
    sm = red[0] + red[1] + red[2] + red[3];
    if (t < 81) att[t] = e / sm;
    __syncthreads();

    float acc = 0.f;
    const float* mr = g_merge + (long)b * 81 * 128 + t;
#pragma unroll 9
    for (int p = 0; p < 81; p++) acc = fmaf(att[p], mr[p * 128], acc);
    pooled[t] = acc;
    __syncthreads();

    if (t < 6) {
        float s2 = bl[t];
        const float* wr = wl + t * 128;
#pragma unroll 8
        for (int o = 0; o < 128; o++) s2 = fmaf(wr[o], pooled[o], s2);
        out[b * 6 + t] = s2;
    }
}

// ============================================================================
extern "C" void kernel_launch(void* const* d_in, const int* in_sizes, int n_in,
                              void* d_out, int out_size)
{
    const float* x    = (const float*)d_in[0];
    const float* w1   = (const float*)d_in[1];
    const float* b1   = (const float*)d_in[2];
    const float* bn1  = (const float*)d_in[3];
    const float* w2   = (const float*)d_in[4];
    const float* b2   = (const float*)d_in[5];
    const float* bn2  = (const float*)d_in[6];
    const float* wgt  = (const float*)d_in[7];
    const float* w3   = (const float*)d_in[8];
    const float* b3   = (const float*)d_in[9];
    const float* bn3  = (const float*)d_in[10];
    const float* w4   = (const float*)d_in[11];
    const float* b4   = (const float*)d_in[12];
    const float* bn4  = (const float*)d_in[13];
    const float* wa1  = (const float*)d_in[14];
    const float* ba1  = (const float*)d_in[15];
    const float* bna  = (const float*)d_in[16];
    const float* wa2  = (const float*)d_in[17];
    const float* ba2  = (const float*)d_in[18];
    const float* wl   = (const float*)d_in[19];
    const float* bl   = (const float*)d_in[20];
    float* out = (float*)d_out;

    cudaFuncSetAttribute(k1_mma, cudaFuncAttributeMaxDynamicSharedMemorySize, K1_SMEM);
    cudaFuncSetAttribute(k2_mma, cudaFuncAttributeMaxDynamicSharedMemorySize, K2_SMEM);
    cudaFuncSetAttribute(k3_mma, cudaFuncAttributeMaxDynamicSharedMemorySize, K3_SMEM);
    cudaFuncSetAttribute(k4_mma, cudaFuncAttributeMaxDynamicSharedMemorySize, K4_SMEM);

    // launch order keeps k2_mma in ncu's sampled slot (4th launch)
    prepA<<<30848, 256>>>(x, w1);                  // 1
    dim3 g1(225, 2);
    k1_mma<<<g1, 256, K1_SMEM>>>(b1, bn1);         // 2
    prepB<<<4568, 256>>>(w2, w3, w4, wgt);         // 3
    k2_mma<<<144, 192, K2_SMEM>>>(b2, bn2);        // 4  <-- profiled, one wave
    k3_mma<<<162, 256, K3_SMEM>>>(b3, bn3);        // 5
    k4_mma<<<162, 256, K4_SMEM>>>(b4, bn4);        // 6
    k5_logits<<<1296, 256>>>(wa1, ba1, bna, wa2, ba2); // 7
    k6_final<<<256, 128>>>(wl, bl, out);           // 8
}